// round 15
// baseline (speedup 1.0000x reference)
#include <cuda_runtime.h>
#include <cuda_bf16.h>
#include <cstdint>

#define Bb   128
#define Ss   416
#define Nn   32
#define Mm   384
#define Dd   256
#define Hh   8
#define Ee   32
#define Oo   256
#define BSs  (Bb*Ss)          // 53248
#define NBH  (Bb*Hh*Ss*Ee)    // 13,631,488

// -------- scratch (static device globals; no runtime allocation) ----------
// fragment-packed weights: [proj(5)][n8t(32)][kc(16)][lane(32)] x 16B
__device__ uint4 g_wf[5*32*16*32];
__device__ __nv_bfloat16 g_qh[NBH], g_ql[NBH];
__device__ __nv_bfloat16 g_kh[NBH], g_kl[NBH];
__device__ __nv_bfloat16 g_vh[NBH], g_vl[NBH];
__device__ float         g_g [NBH];
// fragment-packed attention output: [m8t(6656)][kc(16)][lane(32)] x 16B
__device__ uint4 g_aof[6656*16*32];

__device__ __forceinline__ float warpSum(float v) {
#pragma unroll
    for (int o = 16; o; o >>= 1) v += __shfl_xor_sync(0xffffffffu, v, o);
    return v;
}

// -------- mma.sync helpers --------------------------------------------------
__device__ __forceinline__ uint32_t smem_u32(const void* p) {
    uint32_t a;
    asm("{ .reg .u64 t; cvta.to.shared.u64 t, %1; cvt.u32.u64 %0, t; }"
        : "=r"(a) : "l"(p));
    return a;
}
__device__ __forceinline__ void ldsm4(uint32_t& r0, uint32_t& r1,
                                      uint32_t& r2, uint32_t& r3, uint32_t a) {
    asm volatile("ldmatrix.sync.aligned.m8n8.x4.shared.b16 {%0,%1,%2,%3}, [%4];"
                 : "=r"(r0), "=r"(r1), "=r"(r2), "=r"(r3) : "r"(a));
}
__device__ __forceinline__ void ldsm4t(uint32_t& r0, uint32_t& r1,
                                       uint32_t& r2, uint32_t& r3, uint32_t a) {
    asm volatile("ldmatrix.sync.aligned.m8n8.x4.trans.shared.b16 {%0,%1,%2,%3}, [%4];"
                 : "=r"(r0), "=r"(r1), "=r"(r2), "=r"(r3) : "r"(a));
}
__device__ __forceinline__ void ldsm2(uint32_t& r0, uint32_t& r1, uint32_t a) {
    asm volatile("ldmatrix.sync.aligned.m8n8.x2.shared.b16 {%0,%1}, [%2];"
                 : "=r"(r0), "=r"(r1) : "r"(a));
}
__device__ __forceinline__ void mma16816(float* d, const uint32_t* a,
                                         const uint32_t* b) {
    asm volatile(
        "mma.sync.aligned.m16n8k16.row.col.f32.bf16.bf16.f32 "
        "{%0,%1,%2,%3}, {%4,%5,%6,%7}, {%8,%9}, {%0,%1,%2,%3};"
        : "+f"(d[0]), "+f"(d[1]), "+f"(d[2]), "+f"(d[3])
        : "r"(a[0]), "r"(a[1]), "r"(a[2]), "r"(a[3]), "r"(b[0]), "r"(b[1]));
}
__device__ __forceinline__ void mma1688(float* d, const uint32_t* a, uint32_t b) {
    asm volatile(
        "mma.sync.aligned.m16n8k8.row.col.f32.bf16.bf16.f32 "
        "{%0,%1,%2,%3}, {%4,%5}, {%6}, {%0,%1,%2,%3};"
        : "+f"(d[0]), "+f"(d[1]), "+f"(d[2]), "+f"(d[3])
        : "r"(a[0]), "r"(a[1]), "r"(b));
}
__device__ __forceinline__ void packhl2(float x, float y,
                                        uint32_t& ph, uint32_t& pl) {
    asm("cvt.rn.bf16x2.f32 %0, %1, %2;" : "=r"(ph) : "f"(y), "f"(x));
    float xh = __uint_as_float(ph << 16);
    float yh = __uint_as_float(ph & 0xFFFF0000u);
    float xl = x - xh;
    float yl = y - yh;
    asm("cvt.rn.bf16x2.f32 %0, %1, %2;" : "=r"(pl) : "f"(yl), "f"(xl));
}
__device__ __forceinline__ float ex2f(float x) {
    float r; asm("ex2.approx.f32 %0, %1;" : "=f"(r) : "f"(x)); return r;
}
__device__ __forceinline__ void cpasync16(uint32_t dst, const void* src) {
    asm volatile("cp.async.cg.shared.global [%0], [%1], 16;"
                 :: "r"(dst), "l"(src) : "memory");
}
#define CP_COMMIT() asm volatile("cp.async.commit_group;" ::: "memory")
#define CP_WAIT1()  asm volatile("cp.async.wait_group 1;" ::: "memory")
#define CP_WAIT0()  asm volatile("cp.async.wait_group 0;" ::: "memory")

// ========== Kernel 0: weights -> fragment-packed hi/lo (g_wf) ==============
__global__ void k_wconv(const float* __restrict__ qp, const float* __restrict__ kp,
                        const float* __restrict__ vp, const float* __restrict__ gp,
                        const float* __restrict__ ow) {
    int n8t = blockIdx.x;      // 0..31
    int proj = blockIdx.y;     // 0..4
    int tid = threadIdx.x;     // 512
    int kc = tid >> 5, lane = tid & 31;
    int n = n8t * 8 + (lane >> 2);
    int k0 = kc * 16 + (lane & 3) * 2;
    float v0, v1, v8, v9;
    if (proj < 4) {
        const float* Wp = (proj == 0) ? qp : (proj == 1) ? kp
                         : (proj == 2) ? vp : gp;
        int base = (n >> 5) * 8192 + (n & 31);
        v0 = Wp[base + k0 * 32];
        v1 = Wp[base + (k0 + 1) * 32];
        v8 = Wp[base + (k0 + 8) * 32];
        v9 = Wp[base + (k0 + 9) * 32];
    } else {
        v0 = ow[k0 * 256 + n];
        v1 = ow[(k0 + 1) * 256 + n];
        v8 = ow[(k0 + 8) * 256 + n];
        v9 = ow[(k0 + 9) * 256 + n];
    }
    uint32_t ph0, pl0, ph1, pl1;
    packhl2(v0, v1, ph0, pl0);
    packhl2(v8, v9, ph1, pl1);
    g_wf[((proj * 32 + n8t) * 16 + kc) * 32 + lane] =
        make_uint4(ph0, ph1, pl0, pl1);
}

// ==== Kernel 2: QKVG; fused LN1 A-staging; 2m x 8n warp tiling =============
#define QSCALE 0.2550868099f
#define QK_AHI 0
#define QK_ALO (128*264*2)                 // 67584
#define QKVG_SMEM (2*128*264*2)            // 135168

__global__ void __launch_bounds__(512, 1)
k_qkvg(const float* __restrict__ x, const float* __restrict__ gam,
       const float* __restrict__ bet) {
    extern __shared__ char smq[];
    __nv_bfloat16* Ahi = (__nv_bfloat16*)(smq + QK_AHI);
    __nv_bfloat16* Alo = (__nv_bfloat16*)(smq + QK_ALO);
    uint32_t ahi_b = smem_u32(Ahi), alo_b = smem_u32(Alo);

    int tid = threadIdx.x;
    int wid = tid >> 5, lane = tid & 31;
    int wm = wid >> 3, wn = wid & 7;       // 2 m-slices (64 rows) x 8 n-slices (16)
    int m0 = blockIdx.x * 128;

    // ---- stage A with fused LayerNorm: warp w handles rows w*8..w*8+7 ----
    {
        float4 gm0 = *(const float4*)&gam[lane * 8];
        float4 gm1 = *(const float4*)&gam[lane * 8 + 4];
        float4 bt0 = *(const float4*)&bet[lane * 8];
        float4 bt1 = *(const float4*)&bet[lane * 8 + 4];
#pragma unroll
        for (int r = 0; r < 8; r++) {
            int row = wid * 8 + r;
            const float* xr = x + (size_t)(m0 + row) * 256 + lane * 8;
            float4 v0 = *(const float4*)xr;
            float4 v1 = *(const float4*)(xr + 4);
            float s = v0.x + v0.y + v0.z + v0.w + v1.x + v1.y + v1.z + v1.w;
            s = warpSum(s);
            float mu = s * (1.f / 256.f);
            float d[8] = {v0.x - mu, v0.y - mu, v0.z - mu, v0.w - mu,
                          v1.x - mu, v1.y - mu, v1.z - mu, v1.w - mu};
            float vs = 0.f;
#pragma unroll
            for (int i = 0; i < 8; i++) vs += d[i] * d[i];
            vs = warpSum(vs);
            float rs = rsqrtf(vs * (1.f / 256.f) + 1e-6f);
            float o[8];
            o[0] = d[0] * rs * gm0.x + bt0.x;
            o[1] = d[1] * rs * gm0.y + bt0.y;
            o[2] = d[2] * rs * gm0.z + bt0.z;
            o[3] = d[3] * rs * gm0.w + bt0.w;
            o[4] = d[4] * rs * gm1.x + bt1.x;
            o[5] = d[5] * rs * gm1.y + bt1.y;
            o[6] = d[6] * rs * gm1.z + bt1.z;
            o[7] = d[7] * rs * gm1.w + bt1.w;
            uint32_t ph[4], pl[4];
#pragma unroll
            for (int i = 0; i < 4; i++) packhl2(o[i*2], o[i*2+1], ph[i], pl[i]);
            *(uint4*)&Ahi[row * 264 + lane * 8] = *(uint4*)ph;
            *(uint4*)&Alo[row * 264 + lane * 8] = *(uint4*)pl;
        }
    }
    __syncthreads();   // the ONLY block barrier

    int a_row = lane & 15;
    int a_kof = (lane >> 4) * 8;
    int fr = lane >> 2, fc = lane & 3;

    for (int nt = 0; nt < 8; nt++) {
        int proj = nt >> 1;
        int nin = (nt & 1) * 128;
        int n8b = proj * 32 + (nt & 1) * 16 + wn * 2;

        float acc[4][2][4];
#pragma unroll
        for (int mt = 0; mt < 4; mt++)
#pragma unroll
            for (int j = 0; j < 2; j++)
#pragma unroll
                for (int c = 0; c < 4; c++) acc[mt][j][c] = 0.f;

#pragma unroll 2
        for (int kc = 0; kc < 16; kc++) {
            uint4 bf[2];
#pragma unroll
            for (int j = 0; j < 2; j++)
                bf[j] = g_wf[((n8b + j) * 16 + kc) * 32 + lane];
            uint32_t ah[4][4], al[4][4];
#pragma unroll
            for (int mt = 0; mt < 4; mt++) {
                uint32_t off = (uint32_t)((wm * 64 + mt * 16 + a_row) * 264
                                          + kc * 16 + a_kof) * 2;
                ldsm4(ah[mt][0], ah[mt][1], ah[mt][2], ah[mt][3], ahi_b + off);
                ldsm4(al[mt][0], al[mt][1], al[mt][2], al[mt][3], alo_b + off);
            }
#pragma unroll
            for (int mt = 0; mt < 4; mt++)
#pragma unroll
                for (int j = 0; j < 2; j++) {
                    uint32_t bh[2] = {bf[j].x, bf[j].y};
                    uint32_t bl[2] = {bf[j].z, bf[j].w};
                    mma16816(acc[mt][j], ah[mt], bh);
                    mma16816(acc[mt][j], ah[mt], bl);
                    mma16816(acc[mt][j], al[mt], bh);
                }
        }

        if (proj == 0) {
#pragma unroll
            for (int mt = 0; mt < 4; mt++)
#pragma unroll
                for (int j = 0; j < 2; j++)
#pragma unroll
                    for (int c = 0; c < 4; c++) acc[mt][j][c] *= QSCALE;
        }

        __nv_bfloat16* Oh = (proj == 0) ? g_qh : (proj == 1) ? g_kh : g_vh;
        __nv_bfloat16* Ol = (proj == 0) ? g_ql : (proj == 1) ? g_kl : g_vl;
        bool isG = (proj == 3);
#pragma unroll
        for (int mt = 0; mt < 4; mt++) {
            int m = m0 + wm * 64 + mt * 16 + fr;
            int b1 = m / Ss, s1 = m - b1 * Ss;
            int m2 = m + 8;
            int b2 = m2 / Ss, s2 = m2 - b2 * Ss;
#pragma unroll
            for (int j = 0; j < 2; j++) {
                int n = nin + wn * 16 + j * 8 + fc * 2;
                int h = n >> 5, e = n & 31;
                size_t i1 = (((size_t)(b1 * Hh + h)) * Ss + s1) * Ee + e;
                size_t i2 = (((size_t)(b2 * Hh + h)) * Ss + s2) * Ee + e;
                if (isG) {
                    *(float2*)&g_g[i1] = make_float2(acc[mt][j][0], acc[mt][j][1]);
                    *(float2*)&g_g[i2] = make_float2(acc[mt][j][2], acc[mt][j][3]);
                } else {
                    uint32_t h1, l1, h2, l2;
                    packhl2(acc[mt][j][0], acc[mt][j][1], h1, l1);
                    packhl2(acc[mt][j][2], acc[mt][j][3], h2, l2);
                    *(uint32_t*)&Oh[i1] = h1;
                    *(uint32_t*)&Ol[i1] = l1;
                    *(uint32_t*)&Oh[i2] = h2;
                    *(uint32_t*)&Ol[i2] = l2;
                }
            }
        }
    }
}

// ==== Kernel 3: attention; 2 groups, Q via LDG, log2-domain softmax ========
#define KHI_OFF   0
#define KLO_OFF   33280
#define VH_OFF    66560
#define VL_OFF    99840
#define CSH_OFF   133120
#define RED_OFF   134784
#define OP_OFF    136832
#define ATTN_SMEM 169600

__global__ void __launch_bounds__(512, 1)
k_attn(const float* __restrict__ pmask, const float* __restrict__ mmask) {
    extern __shared__ char smc[];
    __nv_bfloat16* khi = (__nv_bfloat16*)(smc + KHI_OFF);
    __nv_bfloat16* klo = (__nv_bfloat16*)(smc + KLO_OFF);
    __nv_bfloat16* v_h = (__nv_bfloat16*)(smc + VH_OFF);
    __nv_bfloat16* v_l = (__nv_bfloat16*)(smc + VL_OFF);
    float*         c_sh = (float*)(smc + CSH_OFF);
    float*         red  = (float*)(smc + RED_OFF);
    float*         opart = (float*)(smc + OP_OFF);

    uint32_t khi_b = smem_u32(khi), klo_b = smem_u32(klo);
    uint32_t vh_b = smem_u32(v_h), vl_b = smem_u32(v_l);

    int tid = threadIdx.x;
    int lane = tid & 31;
    int bh = blockIdx.x;
    int h = bh & 7, b = bh >> 3;
    size_t baseBH = (size_t)(b * Hh + h) * Ss;

    for (int i = tid; i < Ss * 4; i += 512) {
        int y = i >> 2, q = i & 3;
        size_t src = (baseBH + y) * Ee + q * 8;
        *(uint4*)&khi[y * 40 + q * 8] = *(const uint4*)&g_kh[src];
        *(uint4*)&klo[y * 40 + q * 8] = *(const uint4*)&g_kl[src];
        *(uint4*)&v_h[y * 40 + q * 8] = *(const uint4*)&g_vh[src];
        *(uint4*)&v_l[y * 40 + q * 8] = *(const uint4*)&g_vl[src];
    }
    for (int i = tid; i < Ss; i += 512) {
        float val = (i < Nn) ? pmask[b * Nn + i] : mmask[b * Mm + (i - Nn)];
        c_sh[i] = (val == -2.0f) ? 0.f : 1.f;
    }
    __syncthreads();

    const float BIGL = 1.0e9f;
    int grp = tid >> 8;
    int wg = (tid >> 5) & 7;
    int mh = (wg >> 2) & 1;
    int nq = wg & 3;
    int nbase = nq * 104;
    int gtid = tid & 255;

    int b_row = ((lane >> 4) & 1) * 8 + (lane & 7);
    int b_kof = ((lane >> 3) & 1) * 8;
    int fr = lane >> 2, fc = lane & 3;
    int lx1 = mh * 16 + fr;
    int lx2 = lx1 + 8;

    float* redg = red + grp * 256;
    float* opg  = opart + grp * 4096;
    int bar_id = grp + 1;

    for (int t = grp; t < 13; t += 2) {
        int x0 = t * 32;

        uint32_t qah[2][4], qal[2][4];
        {
            const __nv_bfloat16* ph = g_qh + (baseBH + x0 + lx1) * 32;
            const __nv_bfloat16* pl = g_ql + (baseBH + x0 + lx1) * 32;
#pragma unroll
            for (int ks = 0; ks < 2; ks++) {
                int kk = ks * 16 + fc * 2;
                qah[ks][0] = *(const uint32_t*)&ph[kk];
                qah[ks][1] = *(const uint32_t*)&ph[256 + kk];
                qah[ks][2] = *(const uint32_t*)&ph[kk + 8];
                qah[ks][3] = *(const uint32_t*)&ph[256 + kk + 8];
                qal[ks][0] = *(const uint32_t*)&pl[kk];
                qal[ks][1] = *(const uint32_t*)&pl[256 + kk];
                qal[ks][2] = *(const uint32_t*)&pl[kk + 8];
                qal[ks][3] = *(const uint32_t*)&pl[256 + kk + 8];
            }
        }

        float acc[13][4];
#pragma unroll
        for (int t2 = 0; t2 < 13; t2++)
#pragma unroll
            for (int c = 0; c < 4; c++) acc[t2][c] = 0.f;

#pragma unroll
        for (int ks = 0; ks < 2; ks++) {
            int kk = ks * 16;
#pragma unroll
            for (int jp = 0; jp < 6; jp++) {
                uint32_t bh2[4], bl2[4];
                uint32_t off = (uint32_t)((nbase + jp * 16 + b_row) * 40
                                          + kk + b_kof) * 2;
                ldsm4(bh2[0], bh2[1], bh2[2], bh2[3], khi_b + off);
                ldsm4(bl2[0], bl2[1], bl2[2], bl2[3], klo_b + off);
                mma16816(acc[jp*2],   qah[ks], &bh2[0]);
                mma16816(acc[jp*2],   qah[ks], &bl2[0]);
                mma16816(acc[jp*2],   qal[ks], &bh2[0]);
                mma16816(acc[jp*2+1], qah[ks], &bh2[2]);
                mma16816(acc[jp*2+1], qah[ks], &bl2[2]);
                mma16816(acc[jp*2+1], qal[ks], &bh2[2]);
            }
            {
                uint32_t bh1[2], bl1[2];
                uint32_t off = (uint32_t)((nbase + 96 + (lane & 7)) * 40 + kk
                                          + 8 * ((lane >> 3) & 1)) * 2;
                ldsm2(bh1[0], bh1[1], khi_b + off);
                ldsm2(bl1[0], bl1[1], klo_b + off);
                mma16816(acc[12], qah[ks], bh1);
                mma16816(acc[12], qah[ks], bl1);
                mma16816(acc[12], qal[ks], bh1);
            }
        }

        bool xIsP = (t == 0);
        float cx1 = c_sh[x0 + lx1];
        float cx2 = c_sh[x0 + lx2];
#pragma unroll
        for (int t2 = 0; t2 < 13; t2++) {
            int ybase = nbase + t2 * 8;
            int yc = ybase + fc * 2;
            bool cross = (xIsP != (ybase < Nn));
            float cy0 = c_sh[yc], cy1 = c_sh[yc + 1];
            float by0 = cross ? fmaf(cy0, BIGL, -BIGL) : -BIGL;
            float by1 = cross ? fmaf(cy1, BIGL, -BIGL) : -BIGL;
            acc[t2][0] += by0;
            acc[t2][1] += by1;
            acc[t2][2] += by0;
            acc[t2][3] += by1;
        }

        float m1 = -3.0e38f, m2 = -3.0e38f;
#pragma unroll
        for (int t2 = 0; t2 < 13; t2++) {
            m1 = fmaxf(m1, fmaxf(acc[t2][0], acc[t2][1]));
            m2 = fmaxf(m2, fmaxf(acc[t2][2], acc[t2][3]));
        }
#pragma unroll
        for (int o = 1; o <= 2; o <<= 1) {
            m1 = fmaxf(m1, __shfl_xor_sync(0xffffffffu, m1, o));
            m2 = fmaxf(m2, __shfl_xor_sync(0xffffffffu, m2, o));
        }
        float s1 = 0.f, s2 = 0.f;
#pragma unroll
        for (int t2 = 0; t2 < 13; t2++) {
            acc[t2][0] = ex2f(acc[t2][0] - m1);
            acc[t2][1] = ex2f(acc[t2][1] - m1);
            acc[t2][2] = ex2f(acc[t2][2] - m2);
            acc[t2][3] = ex2f(acc[t2][3] - m2);
            s1 += acc[t2][0] + acc[t2][1];
            s2 += acc[t2][2] + acc[t2][3];
        }
#pragma unroll
        for (int o = 1; o <= 2; o <<= 1) {
            s1 += __shfl_xor_sync(0xffffffffu, s1, o);
            s2 += __shfl_xor_sync(0xffffffffu, s2, o);
        }
        if (fc == 0) {
            redg[lx1 * 8 + nq * 2]     = m1;
            redg[lx1 * 8 + nq * 2 + 1] = s1;
            redg[lx2 * 8 + nq * 2]     = m2;
            redg[lx2 * 8 + nq * 2 + 1] = s2;
        }
        asm volatile("bar.sync %0, %1;" :: "r"(bar_id), "r"(256) : "memory");
        float f1, f2;
        {
            float M1 = -3.0e38f, M2 = -3.0e38f;
#pragma unroll
            for (int q = 0; q < 4; q++) {
                M1 = fmaxf(M1, redg[lx1 * 8 + q * 2]);
                M2 = fmaxf(M2, redg[lx2 * 8 + q * 2]);
            }
            float S1 = 0.f, S2 = 0.f;
#pragma unroll
            for (int q = 0; q < 4; q++) {
                S1 += redg[lx1 * 8 + q * 2 + 1] * ex2f(redg[lx1 * 8 + q * 2] - M1);
                S2 += redg[lx2 * 8 + q * 2 + 1] * ex2f(redg[lx2 * 8 + q * 2] - M2);
            }
            f1 = cx1 * ex2f(m1 - M1) / S1;
            f2 = cx2 * ex2f(m2 - M2) / S2;
        }

        {
            float o[4][4];
#pragma unroll
            for (int eg = 0; eg < 4; eg++)
#pragma unroll
                for (int c = 0; c < 4; c++) o[eg][c] = 0.f;

#pragma unroll
            for (int g = 0; g < 3; g++) {
                uint32_t Ah0[4], Al0[4], Ah1[4], Al1[4];
                {
                    int ta = 4 * g, tb = 4 * g + 1;
                    packhl2(acc[ta][0] * f1, acc[ta][1] * f1, Ah0[0], Al0[0]);
                    packhl2(acc[ta][2] * f2, acc[ta][3] * f2, Ah0[1], Al0[1]);
                    packhl2(acc[tb][0] * f1, acc[tb][1] * f1, Ah0[2], Al0[2]);
                    packhl2(acc[tb][2] * f2, acc[tb][3] * f2, Ah0[3], Al0[3]);
                    int tc = 4 * g + 2, td = 4 * g + 3;
                    packhl2(acc[tc][0] * f1, acc[tc][1] * f1, Ah1[0], Al1[0]);
                    packhl2(acc[tc][2] * f2, acc[tc][3] * f2, Ah1[1], Al1[1]);
                    packhl2(acc[td][0] * f1, acc[td][1] * f1, Ah1[2], Al1[2]);
                    packhl2(acc[td][2] * f2, acc[td][3] * f2, Ah1[3], Al1[3]);
                }
#pragma unroll
                for (int eg = 0; eg < 4; eg++) {
                    uint32_t bh4[4], bl4[4];
                    uint32_t offB = (uint32_t)((nbase + g * 32 + lane) * 40
                                               + eg * 8) * 2;
                    ldsm4t(bh4[0], bh4[1], bh4[2], bh4[3], vh_b + offB);
                    ldsm4t(bl4[0], bl4[1], bl4[2], bl4[3], vl_b + offB);
                    mma16816(o[eg], Ah0, &bh4[0]);
                    mma16816(o[eg], Ah0, &bl4[0]);
                    mma16816(o[eg], Al0, &bh4[0]);
                    mma16816(o[eg], Ah1, &bh4[2]);
                    mma16816(o[eg], Ah1, &bl4[2]);
                    mma16816(o[eg], Al1, &bh4[2]);
                }
            }
            {
                uint32_t Ath[2], Atl[2];
                packhl2(acc[12][0] * f1, acc[12][1] * f1, Ath[0], Atl[0]);
                packhl2(acc[12][2] * f2, acc[12][3] * f2, Ath[1], Atl[1]);
                uint32_t bh4[4], bl4[4];
                uint32_t offT = (uint32_t)((nbase + 96 + (lane & 7)) * 40
                                           + (lane >> 3) * 8) * 2;
                ldsm4t(bh4[0], bh4[1], bh4[2], bh4[3], vh_b + offT);
                ldsm4t(bl4[0], bl4[1], bl4[2], bl4[3], vl_b + offT);
#pragma unroll
                for (int eg = 0; eg < 4; eg++) {
                    mma1688(o[eg], Ath, bh4[eg]);
                    mma1688(o[eg], Ath, bl4[eg]);
                    mma1688(o[eg], Atl, bh4[eg]);
                }
            }
            float* op = opg + nq * 1024;
#pragma unroll
            for (int eg = 0; eg < 4; eg++) {
                int e = eg * 8 + fc * 2;
                *(float2*)&op[lx1 * 32 + e] = make_float2(o[eg][0], o[eg][1]);
                *(float2*)&op[lx2 * 32 + e] = make_float2(o[eg][2], o[eg][3]);
            }
        }
        asm volatile("bar.sync %0, %1;" :: "r"(bar_id), "r"(256) : "memory");

        // ---- reduce over nq + gate + store (fragment-packed g_aof) ----
#pragma unroll
        for (int it = 0; it < 2; it++) {
            int idx = gtid + it * 256;
            int row = idx >> 4;
            int e = (idx & 15) * 2;
            const float* op = opg + row * 32 + e;
            float sum0 = op[0] + op[1024] + op[2048] + op[3072];
            float sum1 = op[1] + op[1025] + op[2049] + op[3073];
            int xs_ = x0 + row;
            float2 gv = *(const float2*)&g_g[(baseBH + xs_) * Ee + e];
            float sg0 = 1.f / (1.f + __expf(-gv.x));
            float sg1 = 1.f / (1.f + __expf(-gv.y));
            float o0 = sum0 * sg0;
            float o1 = sum1 * sg1;
            uint32_t oh, ol;
            packhl2(o0, o1, oh, ol);
            int grow = b * Ss + xs_;
            int m8t = grow >> 3;
            int kglob = h * 32 + e;
            int kc = kglob >> 4;
            int p = (kglob & 15) >> 1;
            int lane2 = (grow & 7) * 4 + (p & 3);
            int slot = p >> 2;
            uint32_t* dst = (uint32_t*)g_aof
                          + ((size_t)(m8t * 16 + kc) * 32 + lane2) * 4;
            dst[slot]     = oh;
            dst[slot + 2] = ol;
        }
    }
}

// ==== Kernel 4: output proj + LN2; A via LDG, B cp.async double-buffered ===
#define OBS_OFF 0                             // 2 stages x 16384 B
#define OYS_OFF 32768                         // 64*264*4 = 67584
#define OMU_OFF 100352
#define ORS_OFF 100608
#define OLN_SMEM 100864

__global__ void __launch_bounds__(512, 1)
k_outln(const float* __restrict__ bias, const float* __restrict__ g2,
        const float* __restrict__ b2, float* __restrict__ out) {
    extern __shared__ char smo[];
    uint4* Bs = (uint4*)(smo + OBS_OFF);      // [stage][n8t(32)][lane(32)]
    float* ys  = (float*)(smo + OYS_OFF);
    float* mus = (float*)(smo + OMU_OFF);
    float* rss = (float*)(smo + ORS_OFF);
    uint32_t bs_b = smem_u32(Bs);

    int tid = threadIdx.x;
    int wid = tid >> 5, lane = tid & 31;
    int mh = wid & 3, nq = wid >> 2;          // 4 m-slices(16) x 4 n-quarters(64)
    int r0 = blockIdx.x * 64;
    int fr = lane >> 2, fc = lane & 3;
    int t0 = (r0 >> 3) + mh * 2;

    auto prefetchB = [&](int kc, int st) {
#pragma unroll
        for (int it = 0; it < 2; it++) {
            int idx = tid + it * 512;          // 0..1023 = n8t*32+lane
            cpasync16(bs_b + (uint32_t)(st * 1024 + idx) * 16,
                      &g_wf[((size_t)(4 * 32 + (idx >> 5)) * 16 + kc) * 32
                            + (idx & 31)]);
        }
        CP_COMMIT();
    };
    prefetchB(0, 0);

    float acc[8][4];
#pragma unroll
    for (int j = 0; j < 8; j++)
#pragma unroll
        for (int c = 0; c < 4; c++) acc[j][c] = 0.f;

    for (int kc = 0; kc < 16; kc++) {
        if (kc < 15) { prefetchB(kc + 1, (kc + 1) & 1); CP_WAIT1(); }
        else         { CP_WAIT0(); }
        __syncthreads();

        uint4 ea = g_aof[((size_t)(t0 * 16 + kc)) * 32 + lane];
        uint4 eb = g_aof[((size_t)((t0 + 1) * 16 + kc)) * 32 + lane];
        uint32_t Ahf[4] = {ea.x, eb.x, ea.y, eb.y};
        uint32_t Alf[4] = {ea.z, eb.z, ea.w, eb.w};

        const uint4* bst = Bs + (kc & 1) * 1024;
#pragma unroll
        for (int jp = 0; jp < 8; jp++) {
            uint4 bf = bst[(nq * 8 + jp) * 32 + lane];
            uint32_t bh[2] = {bf.x, bf.y};
            uint32_t bl[2] = {bf.z, bf.w};
            mma16816(acc[jp], Ahf, bh);
            mma16816(acc[jp], Ahf, bl);
            mma16816(acc[jp], Alf, bh);
        }
        __syncthreads();
    }

    int lx1 = mh * 16 + fr;
    int lx2 = lx1 + 8;
#pragma unroll
    for (int j = 0; j < 8; j++) {
        int n = nq * 64 + j * 8 + fc * 2;
        float b0 = bias[n], b1 = bias[n + 1];
        ys[lx1 * 264 + n]     = acc[j][0] + b0;
        ys[lx1 * 264 + n + 1] = acc[j][1] + b1;
        ys[lx2 * 264 + n]     = acc[j][2] + b0;
        ys[lx2 * 264 + n + 1] = acc[j][3] + b1;
    }
    __syncthreads();

#pragma unroll
    for (int rr = 0; rr < 4; rr++) {
        int xr = wid + rr * 16;
        const float* row = ys + xr * 264;
        float s = 0.f;
#pragma unroll
        for (int j = 0; j < 8; j++) s += row[lane + 32 * j];
        s = warpSum(s);
        float mu = s * (1.f / 256.f);
        float vs = 0.f;
#pragma unroll
        for (int j = 0; j < 8; j++) {
            float d = row[lane + 32 * j] - mu;
            vs += d * d;
        }
        vs = warpSum(vs);
        if (lane == 0) { mus[xr] = mu; rss[xr] = rsqrtf(vs * (1.f / 256.f) + 1e-6f); }
    }
    __syncthreads();

    int cc = tid & 255;
    int rh = tid >> 8;
    float gt = g2[cc], bt = b2[cc];
#pragma unroll 4
    for (int r = rh * 32; r < rh * 32 + 32; r++) {
        out[(size_t)(r0 + r) * 256 + cc] =
            (ys[r * 264 + cc] - mus[r]) * rss[r] * gt + bt;
    }
}

// ===========================================================================
extern "C" void kernel_launch(void* const* d_in, const int* in_sizes, int n_in,
                              void* d_out, int out_size) {
    const float* x   = (const float*)d_in[0];
    const float* pm  = (const float*)d_in[1];
    const float* mm  = (const float*)d_in[2];
    const float* qp  = (const float*)d_in[3];
    const float* kp  = (const float*)d_in[4];
    const float* vp  = (const float*)d_in[5];
    const float* gp  = (const float*)d_in[6];
    const float* ow  = (const float*)d_in[7];
    const float* ob  = (const float*)d_in[8];
    const float* l1g = (const float*)d_in[9];
    const float* l1b = (const float*)d_in[10];
    const float* l2g = (const float*)d_in[11];
    const float* l2b = (const float*)d_in[12];
    float* out = (float*)d_out;

    cudaFuncSetAttribute(k_qkvg, cudaFuncAttributeMaxDynamicSharedMemorySize,
                         QKVG_SMEM);
    cudaFuncSetAttribute(k_attn, cudaFuncAttributeMaxDynamicSharedMemorySize,
                         ATTN_SMEM);
    cudaFuncSetAttribute(k_outln, cudaFuncAttributeMaxDynamicSharedMemorySize,
                         OLN_SMEM);

    k_wconv<<<dim3(32, 5), 512>>>(qp, kp, vp, gp, ow);
    k_qkvg <<<416, 512, QKVG_SMEM>>>(x, l1g, l1b);
    k_attn <<<Bb * Hh, 512, ATTN_SMEM>>>(pm, mm);
    k_outln<<<BSs / 64, 512, OLN_SMEM>>>(ob, l2g, l2b, out);
}

// round 16
// speedup vs baseline: 1.0920x; 1.0920x over previous
#include <cuda_runtime.h>
#include <cuda_bf16.h>
#include <cstdint>

#define Bb   128
#define Ss   416
#define Nn   32
#define Mm   384
#define Dd   256
#define Hh   8
#define Ee   32
#define Oo   256
#define BSs  (Bb*Ss)          // 53248
#define NBH  (Bb*Hh*Ss*Ee)    // 13,631,488

// -------- scratch (static device globals; no runtime allocation) ----------
// fragment-packed weights: [proj(5)][n8t(32)][kc(16)][lane(32)] x 16B
__device__ uint4 g_wf[5*32*16*32];
__device__ __nv_bfloat16 g_qh[NBH], g_ql[NBH];
__device__ __nv_bfloat16 g_kh[NBH], g_kl[NBH];
__device__ __nv_bfloat16 g_vh[NBH], g_vl[NBH];
__device__ float         g_g [NBH];
// fragment-packed attention output: [m8t(6656)][kc(16)][lane(32)] x 16B
__device__ uint4 g_aof[6656*16*32];

__device__ __forceinline__ float warpSum(float v) {
#pragma unroll
    for (int o = 16; o; o >>= 1) v += __shfl_xor_sync(0xffffffffu, v, o);
    return v;
}

// -------- mma.sync helpers --------------------------------------------------
__device__ __forceinline__ uint32_t smem_u32(const void* p) {
    uint32_t a;
    asm("{ .reg .u64 t; cvta.to.shared.u64 t, %1; cvt.u32.u64 %0, t; }"
        : "=r"(a) : "l"(p));
    return a;
}
__device__ __forceinline__ void ldsm4(uint32_t& r0, uint32_t& r1,
                                      uint32_t& r2, uint32_t& r3, uint32_t a) {
    asm volatile("ldmatrix.sync.aligned.m8n8.x4.shared.b16 {%0,%1,%2,%3}, [%4];"
                 : "=r"(r0), "=r"(r1), "=r"(r2), "=r"(r3) : "r"(a));
}
__device__ __forceinline__ void ldsm4t(uint32_t& r0, uint32_t& r1,
                                       uint32_t& r2, uint32_t& r3, uint32_t a) {
    asm volatile("ldmatrix.sync.aligned.m8n8.x4.trans.shared.b16 {%0,%1,%2,%3}, [%4];"
                 : "=r"(r0), "=r"(r1), "=r"(r2), "=r"(r3) : "r"(a));
}
__device__ __forceinline__ void ldsm2(uint32_t& r0, uint32_t& r1, uint32_t a) {
    asm volatile("ldmatrix.sync.aligned.m8n8.x2.shared.b16 {%0,%1}, [%2];"
                 : "=r"(r0), "=r"(r1) : "r"(a));
}
__device__ __forceinline__ void mma16816(float* d, const uint32_t* a,
                                         const uint32_t* b) {
    asm volatile(
        "mma.sync.aligned.m16n8k16.row.col.f32.bf16.bf16.f32 "
        "{%0,%1,%2,%3}, {%4,%5,%6,%7}, {%8,%9}, {%0,%1,%2,%3};"
        : "+f"(d[0]), "+f"(d[1]), "+f"(d[2]), "+f"(d[3])
        : "r"(a[0]), "r"(a[1]), "r"(a[2]), "r"(a[3]), "r"(b[0]), "r"(b[1]));
}
__device__ __forceinline__ void mma1688(float* d, const uint32_t* a, uint32_t b) {
    asm volatile(
        "mma.sync.aligned.m16n8k8.row.col.f32.bf16.bf16.f32 "
        "{%0,%1,%2,%3}, {%4,%5}, {%6}, {%0,%1,%2,%3};"
        : "+f"(d[0]), "+f"(d[1]), "+f"(d[2]), "+f"(d[3])
        : "r"(a[0]), "r"(a[1]), "r"(b));
}
__device__ __forceinline__ void packhl2(float x, float y,
                                        uint32_t& ph, uint32_t& pl) {
    asm("cvt.rn.bf16x2.f32 %0, %1, %2;" : "=r"(ph) : "f"(y), "f"(x));
    float xh = __uint_as_float(ph << 16);
    float yh = __uint_as_float(ph & 0xFFFF0000u);
    float xl = x - xh;
    float yl = y - yh;
    asm("cvt.rn.bf16x2.f32 %0, %1, %2;" : "=r"(pl) : "f"(yl), "f"(xl));
}
__device__ __forceinline__ float ex2f(float x) {
    float r; asm("ex2.approx.f32 %0, %1;" : "=f"(r) : "f"(x)); return r;
}
__device__ __forceinline__ void cpasync16(uint32_t dst, const void* src) {
    asm volatile("cp.async.cg.shared.global [%0], [%1], 16;"
                 :: "r"(dst), "l"(src) : "memory");
}
#define CP_COMMIT() asm volatile("cp.async.commit_group;" ::: "memory")
#define CP_WAIT1()  asm volatile("cp.async.wait_group 1;" ::: "memory")
#define CP_WAIT0()  asm volatile("cp.async.wait_group 0;" ::: "memory")

// ========== Kernel 0: weights -> fragment-packed hi/lo (g_wf) ==============
__global__ void k_wconv(const float* __restrict__ qp, const float* __restrict__ kp,
                        const float* __restrict__ vp, const float* __restrict__ gp,
                        const float* __restrict__ ow) {
    int n8t = blockIdx.x;      // 0..31
    int proj = blockIdx.y;     // 0..4
    int tid = threadIdx.x;     // 512
    int kc = tid >> 5, lane = tid & 31;
    int n = n8t * 8 + (lane >> 2);
    int k0 = kc * 16 + (lane & 3) * 2;
    float v0, v1, v8, v9;
    if (proj < 4) {
        const float* Wp = (proj == 0) ? qp : (proj == 1) ? kp
                         : (proj == 2) ? vp : gp;
        int base = (n >> 5) * 8192 + (n & 31);
        v0 = Wp[base + k0 * 32];
        v1 = Wp[base + (k0 + 1) * 32];
        v8 = Wp[base + (k0 + 8) * 32];
        v9 = Wp[base + (k0 + 9) * 32];
    } else {
        v0 = ow[k0 * 256 + n];
        v1 = ow[(k0 + 1) * 256 + n];
        v8 = ow[(k0 + 8) * 256 + n];
        v9 = ow[(k0 + 9) * 256 + n];
    }
    uint32_t ph0, pl0, ph1, pl1;
    packhl2(v0, v1, ph0, pl0);
    packhl2(v8, v9, ph1, pl1);
    g_wf[((proj * 32 + n8t) * 16 + kc) * 32 + lane] =
        make_uint4(ph0, ph1, pl0, pl1);
}

// ==== Kernel 2: QKVG; fused LN1 A-staging; B fragments reg-prefetched ======
#define QSCALE 0.2550868099f
#define QK_AHI 0
#define QK_ALO (128*264*2)                 // 67584
#define QKVG_SMEM (2*128*264*2)            // 135168

__global__ void __launch_bounds__(512, 1)
k_qkvg(const float* __restrict__ x, const float* __restrict__ gam,
       const float* __restrict__ bet) {
    extern __shared__ char smq[];
    __nv_bfloat16* Ahi = (__nv_bfloat16*)(smq + QK_AHI);
    __nv_bfloat16* Alo = (__nv_bfloat16*)(smq + QK_ALO);
    uint32_t ahi_b = smem_u32(Ahi), alo_b = smem_u32(Alo);

    int tid = threadIdx.x;
    int wid = tid >> 5, lane = tid & 31;
    int wm = wid >> 3, wn = wid & 7;       // 2 m-slices (64 rows) x 8 n-slices (16)
    int m0 = blockIdx.x * 128;

    // ---- stage A with fused LayerNorm: warp w handles rows w*8..w*8+7 ----
    {
        float4 gm0 = *(const float4*)&gam[lane * 8];
        float4 gm1 = *(const float4*)&gam[lane * 8 + 4];
        float4 bt0 = *(const float4*)&bet[lane * 8];
        float4 bt1 = *(const float4*)&bet[lane * 8 + 4];
#pragma unroll
        for (int r = 0; r < 8; r++) {
            int row = wid * 8 + r;
            const float* xr = x + (size_t)(m0 + row) * 256 + lane * 8;
            float4 v0 = *(const float4*)xr;
            float4 v1 = *(const float4*)(xr + 4);
            float s = v0.x + v0.y + v0.z + v0.w + v1.x + v1.y + v1.z + v1.w;
            s = warpSum(s);
            float mu = s * (1.f / 256.f);
            float d[8] = {v0.x - mu, v0.y - mu, v0.z - mu, v0.w - mu,
                          v1.x - mu, v1.y - mu, v1.z - mu, v1.w - mu};
            float vs = 0.f;
#pragma unroll
            for (int i = 0; i < 8; i++) vs += d[i] * d[i];
            vs = warpSum(vs);
            float rs = rsqrtf(vs * (1.f / 256.f) + 1e-6f);
            float o[8];
            o[0] = d[0] * rs * gm0.x + bt0.x;
            o[1] = d[1] * rs * gm0.y + bt0.y;
            o[2] = d[2] * rs * gm0.z + bt0.z;
            o[3] = d[3] * rs * gm0.w + bt0.w;
            o[4] = d[4] * rs * gm1.x + bt1.x;
            o[5] = d[5] * rs * gm1.y + bt1.y;
            o[6] = d[6] * rs * gm1.z + bt1.z;
            o[7] = d[7] * rs * gm1.w + bt1.w;
            uint32_t ph[4], pl[4];
#pragma unroll
            for (int i = 0; i < 4; i++) packhl2(o[i*2], o[i*2+1], ph[i], pl[i]);
            *(uint4*)&Ahi[row * 264 + lane * 8] = *(uint4*)ph;
            *(uint4*)&Alo[row * 264 + lane * 8] = *(uint4*)pl;
        }
    }
    __syncthreads();   // the ONLY block barrier

    int a_row = lane & 15;
    int a_kof = (lane >> 4) * 8;
    int fr = lane >> 2, fc = lane & 3;

    for (int nt = 0; nt < 8; nt++) {
        int proj = nt >> 1;
        int nin = (nt & 1) * 128;
        int n8b = proj * 32 + (nt & 1) * 16 + wn * 2;
        const uint4* pb = g_wf + ((size_t)n8b * 16) * 32 + lane;

        float acc[4][2][4];
#pragma unroll
        for (int mt = 0; mt < 4; mt++)
#pragma unroll
            for (int j = 0; j < 2; j++)
#pragma unroll
                for (int c = 0; c < 4; c++) acc[mt][j][c] = 0.f;

        // register-prefetched B fragments
        uint4 bf[2];
        bf[0] = pb[0];
        bf[1] = pb[512];

#pragma unroll 2
        for (int kc = 0; kc < 16; kc++) {
            uint4 bfn[2];
            if (kc < 15) {
                bfn[0] = pb[(kc + 1) * 32];
                bfn[1] = pb[512 + (kc + 1) * 32];
            }
            uint32_t ah[4][4], al[4][4];
#pragma unroll
            for (int mt = 0; mt < 4; mt++) {
                uint32_t off = (uint32_t)((wm * 64 + mt * 16 + a_row) * 264
                                          + kc * 16 + a_kof) * 2;
                ldsm4(ah[mt][0], ah[mt][1], ah[mt][2], ah[mt][3], ahi_b + off);
                ldsm4(al[mt][0], al[mt][1], al[mt][2], al[mt][3], alo_b + off);
            }
#pragma unroll
            for (int mt = 0; mt < 4; mt++)
#pragma unroll
                for (int j = 0; j < 2; j++) {
                    uint32_t bh[2] = {bf[j].x, bf[j].y};
                    uint32_t bl[2] = {bf[j].z, bf[j].w};
                    mma16816(acc[mt][j], ah[mt], bh);
                    mma16816(acc[mt][j], ah[mt], bl);
                    mma16816(acc[mt][j], al[mt], bh);
                }
            bf[0] = bfn[0];
            bf[1] = bfn[1];
        }

        if (proj == 0) {
#pragma unroll
            for (int mt = 0; mt < 4; mt++)
#pragma unroll
                for (int j = 0; j < 2; j++)
#pragma unroll
                    for (int c = 0; c < 4; c++) acc[mt][j][c] *= QSCALE;
        }

        __nv_bfloat16* Oh = (proj == 0) ? g_qh : (proj == 1) ? g_kh : g_vh;
        __nv_bfloat16* Ol = (proj == 0) ? g_ql : (proj == 1) ? g_kl : g_vl;
        bool isG = (proj == 3);
#pragma unroll
        for (int mt = 0; mt < 4; mt++) {
            int m = m0 + wm * 64 + mt * 16 + fr;
            int b1 = m / Ss, s1 = m - b1 * Ss;
            int m2 = m + 8;
            int b2 = m2 / Ss, s2 = m2 - b2 * Ss;
#pragma unroll
            for (int j = 0; j < 2; j++) {
                int n = nin + wn * 16 + j * 8 + fc * 2;
                int h = n >> 5, e = n & 31;
                size_t i1 = (((size_t)(b1 * Hh + h)) * Ss + s1) * Ee + e;
                size_t i2 = (((size_t)(b2 * Hh + h)) * Ss + s2) * Ee + e;
                if (isG) {
                    *(float2*)&g_g[i1] = make_float2(acc[mt][j][0], acc[mt][j][1]);
                    *(float2*)&g_g[i2] = make_float2(acc[mt][j][2], acc[mt][j][3]);
                } else {
                    uint32_t h1, l1, h2, l2;
                    packhl2(acc[mt][j][0], acc[mt][j][1], h1, l1);
                    packhl2(acc[mt][j][2], acc[mt][j][3], h2, l2);
                    *(uint32_t*)&Oh[i1] = h1;
                    *(uint32_t*)&Ol[i1] = l1;
                    *(uint32_t*)&Oh[i2] = h2;
                    *(uint32_t*)&Ol[i2] = l2;
                }
            }
        }
    }
}

// ==== Kernel 3: attention; 2 groups, Q via LDG, log2-domain softmax ========
#define KHI_OFF   0
#define KLO_OFF   33280
#define VH_OFF    66560
#define VL_OFF    99840
#define CSH_OFF   133120
#define RED_OFF   134784
#define OP_OFF    136832
#define ATTN_SMEM 169600

__global__ void __launch_bounds__(512, 1)
k_attn(const float* __restrict__ pmask, const float* __restrict__ mmask) {
    extern __shared__ char smc[];
    __nv_bfloat16* khi = (__nv_bfloat16*)(smc + KHI_OFF);
    __nv_bfloat16* klo = (__nv_bfloat16*)(smc + KLO_OFF);
    __nv_bfloat16* v_h = (__nv_bfloat16*)(smc + VH_OFF);
    __nv_bfloat16* v_l = (__nv_bfloat16*)(smc + VL_OFF);
    float*         c_sh = (float*)(smc + CSH_OFF);
    float*         red  = (float*)(smc + RED_OFF);
    float*         opart = (float*)(smc + OP_OFF);

    uint32_t khi_b = smem_u32(khi), klo_b = smem_u32(klo);
    uint32_t vh_b = smem_u32(v_h), vl_b = smem_u32(v_l);

    int tid = threadIdx.x;
    int lane = tid & 31;
    int bh = blockIdx.x;
    int h = bh & 7, b = bh >> 3;
    size_t baseBH = (size_t)(b * Hh + h) * Ss;

    for (int i = tid; i < Ss * 4; i += 512) {
        int y = i >> 2, q = i & 3;
        size_t src = (baseBH + y) * Ee + q * 8;
        *(uint4*)&khi[y * 40 + q * 8] = *(const uint4*)&g_kh[src];
        *(uint4*)&klo[y * 40 + q * 8] = *(const uint4*)&g_kl[src];
        *(uint4*)&v_h[y * 40 + q * 8] = *(const uint4*)&g_vh[src];
        *(uint4*)&v_l[y * 40 + q * 8] = *(const uint4*)&g_vl[src];
    }
    for (int i = tid; i < Ss; i += 512) {
        float val = (i < Nn) ? pmask[b * Nn + i] : mmask[b * Mm + (i - Nn)];
        c_sh[i] = (val == -2.0f) ? 0.f : 1.f;
    }
    __syncthreads();

    const float BIGL = 1.0e9f;
    int grp = tid >> 8;
    int wg = (tid >> 5) & 7;
    int mh = (wg >> 2) & 1;
    int nq = wg & 3;
    int nbase = nq * 104;
    int gtid = tid & 255;

    int b_row = ((lane >> 4) & 1) * 8 + (lane & 7);
    int b_kof = ((lane >> 3) & 1) * 8;
    int fr = lane >> 2, fc = lane & 3;
    int lx1 = mh * 16 + fr;
    int lx2 = lx1 + 8;

    float* redg = red + grp * 256;
    float* opg  = opart + grp * 4096;
    int bar_id = grp + 1;

    for (int t = grp; t < 13; t += 2) {
        int x0 = t * 32;

        uint32_t qah[2][4], qal[2][4];
        {
            const __nv_bfloat16* ph = g_qh + (baseBH + x0 + lx1) * 32;
            const __nv_bfloat16* pl = g_ql + (baseBH + x0 + lx1) * 32;
#pragma unroll
            for (int ks = 0; ks < 2; ks++) {
                int kk = ks * 16 + fc * 2;
                qah[ks][0] = *(const uint32_t*)&ph[kk];
                qah[ks][1] = *(const uint32_t*)&ph[256 + kk];
                qah[ks][2] = *(const uint32_t*)&ph[kk + 8];
                qah[ks][3] = *(const uint32_t*)&ph[256 + kk + 8];
                qal[ks][0] = *(const uint32_t*)&pl[kk];
                qal[ks][1] = *(const uint32_t*)&pl[256 + kk];
                qal[ks][2] = *(const uint32_t*)&pl[kk + 8];
                qal[ks][3] = *(const uint32_t*)&pl[256 + kk + 8];
            }
        }

        float acc[13][4];
#pragma unroll
        for (int t2 = 0; t2 < 13; t2++)
#pragma unroll
            for (int c = 0; c < 4; c++) acc[t2][c] = 0.f;

#pragma unroll
        for (int ks = 0; ks < 2; ks++) {
            int kk = ks * 16;
#pragma unroll
            for (int jp = 0; jp < 6; jp++) {
                uint32_t bh2[4], bl2[4];
                uint32_t off = (uint32_t)((nbase + jp * 16 + b_row) * 40
                                          + kk + b_kof) * 2;
                ldsm4(bh2[0], bh2[1], bh2[2], bh2[3], khi_b + off);
                ldsm4(bl2[0], bl2[1], bl2[2], bl2[3], klo_b + off);
                mma16816(acc[jp*2],   qah[ks], &bh2[0]);
                mma16816(acc[jp*2],   qah[ks], &bl2[0]);
                mma16816(acc[jp*2],   qal[ks], &bh2[0]);
                mma16816(acc[jp*2+1], qah[ks], &bh2[2]);
                mma16816(acc[jp*2+1], qah[ks], &bl2[2]);
                mma16816(acc[jp*2+1], qal[ks], &bh2[2]);
            }
            {
                uint32_t bh1[2], bl1[2];
                uint32_t off = (uint32_t)((nbase + 96 + (lane & 7)) * 40 + kk
                                          + 8 * ((lane >> 3) & 1)) * 2;
                ldsm2(bh1[0], bh1[1], khi_b + off);
                ldsm2(bl1[0], bl1[1], klo_b + off);
                mma16816(acc[12], qah[ks], bh1);
                mma16816(acc[12], qah[ks], bl1);
                mma16816(acc[12], qal[ks], bh1);
            }
        }

        bool xIsP = (t == 0);
        float cx1 = c_sh[x0 + lx1];
        float cx2 = c_sh[x0 + lx2];
#pragma unroll
        for (int t2 = 0; t2 < 13; t2++) {
            int ybase = nbase + t2 * 8;
            int yc = ybase + fc * 2;
            bool cross = (xIsP != (ybase < Nn));
            float cy0 = c_sh[yc], cy1 = c_sh[yc + 1];
            float by0 = cross ? fmaf(cy0, BIGL, -BIGL) : -BIGL;
            float by1 = cross ? fmaf(cy1, BIGL, -BIGL) : -BIGL;
            acc[t2][0] += by0;
            acc[t2][1] += by1;
            acc[t2][2] += by0;
            acc[t2][3] += by1;
        }

        float m1 = -3.0e38f, m2 = -3.0e38f;
#pragma unroll
        for (int t2 = 0; t2 < 13; t2++) {
            m1 = fmaxf(m1, fmaxf(acc[t2][0], acc[t2][1]));
            m2 = fmaxf(m2, fmaxf(acc[t2][2], acc[t2][3]));
        }
#pragma unroll
        for (int o = 1; o <= 2; o <<= 1) {
            m1 = fmaxf(m1, __shfl_xor_sync(0xffffffffu, m1, o));
            m2 = fmaxf(m2, __shfl_xor_sync(0xffffffffu, m2, o));
        }
        float s1 = 0.f, s2 = 0.f;
#pragma unroll
        for (int t2 = 0; t2 < 13; t2++) {
            acc[t2][0] = ex2f(acc[t2][0] - m1);
            acc[t2][1] = ex2f(acc[t2][1] - m1);
            acc[t2][2] = ex2f(acc[t2][2] - m2);
            acc[t2][3] = ex2f(acc[t2][3] - m2);
            s1 += acc[t2][0] + acc[t2][1];
            s2 += acc[t2][2] + acc[t2][3];
        }
#pragma unroll
        for (int o = 1; o <= 2; o <<= 1) {
            s1 += __shfl_xor_sync(0xffffffffu, s1, o);
            s2 += __shfl_xor_sync(0xffffffffu, s2, o);
        }
        if (fc == 0) {
            redg[lx1 * 8 + nq * 2]     = m1;
            redg[lx1 * 8 + nq * 2 + 1] = s1;
            redg[lx2 * 8 + nq * 2]     = m2;
            redg[lx2 * 8 + nq * 2 + 1] = s2;
        }
        asm volatile("bar.sync %0, %1;" :: "r"(bar_id), "r"(256) : "memory");
        float f1, f2;
        {
            float M1 = -3.0e38f, M2 = -3.0e38f;
#pragma unroll
            for (int q = 0; q < 4; q++) {
                M1 = fmaxf(M1, redg[lx1 * 8 + q * 2]);
                M2 = fmaxf(M2, redg[lx2 * 8 + q * 2]);
            }
            float S1 = 0.f, S2 = 0.f;
#pragma unroll
            for (int q = 0; q < 4; q++) {
                S1 += redg[lx1 * 8 + q * 2 + 1] * ex2f(redg[lx1 * 8 + q * 2] - M1);
                S2 += redg[lx2 * 8 + q * 2 + 1] * ex2f(redg[lx2 * 8 + q * 2] - M2);
            }
            f1 = cx1 * ex2f(m1 - M1) / S1;
            f2 = cx2 * ex2f(m2 - M2) / S2;
        }

        {
            float o[4][4];
#pragma unroll
            for (int eg = 0; eg < 4; eg++)
#pragma unroll
                for (int c = 0; c < 4; c++) o[eg][c] = 0.f;

#pragma unroll
            for (int g = 0; g < 3; g++) {
                uint32_t Ah0[4], Al0[4], Ah1[4], Al1[4];
                {
                    int ta = 4 * g, tb = 4 * g + 1;
                    packhl2(acc[ta][0] * f1, acc[ta][1] * f1, Ah0[0], Al0[0]);
                    packhl2(acc[ta][2] * f2, acc[ta][3] * f2, Ah0[1], Al0[1]);
                    packhl2(acc[tb][0] * f1, acc[tb][1] * f1, Ah0[2], Al0[2]);
                    packhl2(acc[tb][2] * f2, acc[tb][3] * f2, Ah0[3], Al0[3]);
                    int tc = 4 * g + 2, td = 4 * g + 3;
                    packhl2(acc[tc][0] * f1, acc[tc][1] * f1, Ah1[0], Al1[0]);
                    packhl2(acc[tc][2] * f2, acc[tc][3] * f2, Ah1[1], Al1[1]);
                    packhl2(acc[td][0] * f1, acc[td][1] * f1, Ah1[2], Al1[2]);
                    packhl2(acc[td][2] * f2, acc[td][3] * f2, Ah1[3], Al1[3]);
                }
#pragma unroll
                for (int eg = 0; eg < 4; eg++) {
                    uint32_t bh4[4], bl4[4];
                    uint32_t offB = (uint32_t)((nbase + g * 32 + lane) * 40
                                               + eg * 8) * 2;
                    ldsm4t(bh4[0], bh4[1], bh4[2], bh4[3], vh_b + offB);
                    ldsm4t(bl4[0], bl4[1], bl4[2], bl4[3], vl_b + offB);
                    mma16816(o[eg], Ah0, &bh4[0]);
                    mma16816(o[eg], Ah0, &bl4[0]);
                    mma16816(o[eg], Al0, &bh4[0]);
                    mma16816(o[eg], Ah1, &bh4[2]);
                    mma16816(o[eg], Ah1, &bl4[2]);
                    mma16816(o[eg], Al1, &bh4[2]);
                }
            }
            {
                uint32_t Ath[2], Atl[2];
                packhl2(acc[12][0] * f1, acc[12][1] * f1, Ath[0], Atl[0]);
                packhl2(acc[12][2] * f2, acc[12][3] * f2, Ath[1], Atl[1]);
                uint32_t bh4[4], bl4[4];
                uint32_t offT = (uint32_t)((nbase + 96 + (lane & 7)) * 40
                                           + (lane >> 3) * 8) * 2;
                ldsm4t(bh4[0], bh4[1], bh4[2], bh4[3], vh_b + offT);
                ldsm4t(bl4[0], bl4[1], bl4[2], bl4[3], vl_b + offT);
#pragma unroll
                for (int eg = 0; eg < 4; eg++) {
                    mma1688(o[eg], Ath, bh4[eg]);
                    mma1688(o[eg], Ath, bl4[eg]);
                    mma1688(o[eg], Atl, bh4[eg]);
                }
            }
            float* op = opg + nq * 1024;
#pragma unroll
            for (int eg = 0; eg < 4; eg++) {
                int e = eg * 8 + fc * 2;
                *(float2*)&op[lx1 * 32 + e] = make_float2(o[eg][0], o[eg][1]);
                *(float2*)&op[lx2 * 32 + e] = make_float2(o[eg][2], o[eg][3]);
            }
        }
        asm volatile("bar.sync %0, %1;" :: "r"(bar_id), "r"(256) : "memory");

        // ---- reduce over nq + gate + store (fragment-packed g_aof) ----
#pragma unroll
        for (int it = 0; it < 2; it++) {
            int idx = gtid + it * 256;
            int row = idx >> 4;
            int e = (idx & 15) * 2;
            const float* op = opg + row * 32 + e;
            float sum0 = op[0] + op[1024] + op[2048] + op[3072];
            float sum1 = op[1] + op[1025] + op[2049] + op[3073];
            int xs_ = x0 + row;
            float2 gv = *(const float2*)&g_g[(baseBH + xs_) * Ee + e];
            float sg0 = 1.f / (1.f + __expf(-gv.x));
            float sg1 = 1.f / (1.f + __expf(-gv.y));
            float o0 = sum0 * sg0;
            float o1 = sum1 * sg1;
            uint32_t oh, ol;
            packhl2(o0, o1, oh, ol);
            int grow = b * Ss + xs_;
            int m8t = grow >> 3;
            int kglob = h * 32 + e;
            int kc = kglob >> 4;
            int p = (kglob & 15) >> 1;
            int lane2 = (grow & 7) * 4 + (p & 3);
            int slot = p >> 2;
            uint32_t* dst = (uint32_t*)g_aof
                          + ((size_t)(m8t * 16 + kc) * 32 + lane2) * 4;
            dst[slot]     = oh;
            dst[slot + 2] = ol;
        }
    }
}

// ==== Kernel 4: output proj + LN2; reg-prefetched A, cp.async B ============
#define OBS_OFF 0                             // 2 stages x 16384 B
#define OYS_OFF 32768                         // 64*264*4 = 67584
#define OMU_OFF 100352
#define ORS_OFF 100608
#define OLN_SMEM 100864

__global__ void __launch_bounds__(512, 1)
k_outln(const float* __restrict__ bias, const float* __restrict__ g2,
        const float* __restrict__ b2, float* __restrict__ out) {
    extern __shared__ char smo[];
    uint4* Bs = (uint4*)(smo + OBS_OFF);      // [stage][n8t(32)][lane(32)]
    float* ys  = (float*)(smo + OYS_OFF);
    float* mus = (float*)(smo + OMU_OFF);
    float* rss = (float*)(smo + ORS_OFF);
    uint32_t bs_b = smem_u32(Bs);

    int tid = threadIdx.x;
    int wid = tid >> 5, lane = tid & 31;
    int mh = wid & 3, nq = wid >> 2;          // 4 m-slices(16) x 4 n-quarters(64)
    int r0 = blockIdx.x * 64;
    int fr = lane >> 2, fc = lane & 3;
    int t0 = (r0 >> 3) + mh * 2;

    const uint4* pa0 = g_aof + (size_t)t0 * 16 * 32 + lane;
    const uint4* pa1 = pa0 + 16 * 32;

    auto prefetchB = [&](int kc, int st) {
#pragma unroll
        for (int it = 0; it < 2; it++) {
            int idx = tid + it * 512;          // 0..1023 = n8t*32+lane
            cpasync16(bs_b + (uint32_t)(st * 1024 + idx) * 16,
                      &g_wf[((size_t)(4 * 32 + (idx >> 5)) * 16 + kc) * 32
                            + (idx & 31)]);
        }
        CP_COMMIT();
    };
    prefetchB(0, 0);

    float acc[8][4];
#pragma unroll
    for (int j = 0; j < 8; j++)
#pragma unroll
        for (int c = 0; c < 4; c++) acc[j][c] = 0.f;

    // register-prefetched A fragments
    uint4 ea = pa0[0], eb = pa1[0];

    for (int kc = 0; kc < 16; kc++) {
        if (kc < 15) { prefetchB(kc + 1, (kc + 1) & 1); CP_WAIT1(); }
        else         { CP_WAIT0(); }
        __syncthreads();

        uint4 ea_n, eb_n;
        if (kc < 15) {
            ea_n = pa0[(kc + 1) * 32];
            eb_n = pa1[(kc + 1) * 32];
        }

        uint32_t Ahf[4] = {ea.x, eb.x, ea.y, eb.y};
        uint32_t Alf[4] = {ea.z, eb.z, ea.w, eb.w};

        const uint4* bst = Bs + (kc & 1) * 1024;
#pragma unroll
        for (int jp = 0; jp < 8; jp++) {
            uint4 bf = bst[(nq * 8 + jp) * 32 + lane];
            uint32_t bh[2] = {bf.x, bf.y};
            uint32_t bl[2] = {bf.z, bf.w};
            mma16816(acc[jp], Ahf, bh);
            mma16816(acc[jp], Ahf, bl);
            mma16816(acc[jp], Alf, bh);
        }
        __syncthreads();
        ea = ea_n;
        eb = eb_n;
    }

    int lx1 = mh * 16 + fr;
    int lx2 = lx1 + 8;
#pragma unroll
    for (int j = 0; j < 8; j++) {
        int n = nq * 64 + j * 8 + fc * 2;
        float b0 = bias[n], b1 = bias[n + 1];
        ys[lx1 * 264 + n]     = acc[j][0] + b0;
        ys[lx1 * 264 + n + 1] = acc[j][1] + b1;
        ys[lx2 * 264 + n]     = acc[j][2] + b0;
        ys[lx2 * 264 + n + 1] = acc[j][3] + b1;
    }
    __syncthreads();

#pragma unroll
    for (int rr = 0; rr < 4; rr++) {
        int xr = wid + rr * 16;
        const float* row = ys + xr * 264;
        float s = 0.f;
#pragma unroll
        for (int j = 0; j < 8; j++) s += row[lane + 32 * j];
        s = warpSum(s);
        float mu = s * (1.f / 256.f);
        float vs = 0.f;
#pragma unroll
        for (int j = 0; j < 8; j++) {
            float d = row[lane + 32 * j] - mu;
            vs += d * d;
        }
        vs = warpSum(vs);
        if (lane == 0) { mus[xr] = mu; rss[xr] = rsqrtf(vs * (1.f / 256.f) + 1e-6f); }
    }
    __syncthreads();

    int cc = tid & 255;
    int rh = tid >> 8;
    float gt = g2[cc], bt = b2[cc];
#pragma unroll 4
    for (int r = rh * 32; r < rh * 32 + 32; r++) {
        out[(size_t)(r0 + r) * 256 + cc] =
            (ys[r * 264 + cc] - mus[r]) * rss[r] * gt + bt;
    }
}

// ===========================================================================
extern "C" void kernel_launch(void* const* d_in, const int* in_sizes, int n_in,
                              void* d_out, int out_size) {
    const float* x   = (const float*)d_in[0];
    const float* pm  = (const float*)d_in[1];
    const float* mm  = (const float*)d_in[2];
    const float* qp  = (const float*)d_in[3];
    const float* kp  = (const float*)d_in[4];
    const float* vp  = (const float*)d_in[5];
    const float* gp  = (const float*)d_in[6];
    const float* ow  = (const float*)d_in[7];
    const float* ob  = (const float*)d_in[8];
    const float* l1g = (const float*)d_in[9];
    const float* l1b = (const float*)d_in[10];
    const float* l2g = (const float*)d_in[11];
    const float* l2b = (const float*)d_in[12];
    float* out = (float*)d_out;

    cudaFuncSetAttribute(k_qkvg, cudaFuncAttributeMaxDynamicSharedMemorySize,
                         QKVG_SMEM);
    cudaFuncSetAttribute(k_attn, cudaFuncAttributeMaxDynamicSharedMemorySize,
                         ATTN_SMEM);
    cudaFuncSetAttribute(k_outln, cudaFuncAttributeMaxDynamicSharedMemorySize,
                         OLN_SMEM);

    k_wconv<<<dim3(32, 5), 512>>>(qp, kp, vp, gp, ow);
    k_qkvg <<<416, 512, QKVG_SMEM>>>(x, l1g, l1b);
    k_attn <<<Bb * Hh, 512, ATTN_SMEM>>>(pm, mm);
    k_outln<<<BSs / 64, 512, OLN_SMEM>>>(ob, l2g, l2b, out);
}

// round 17
// speedup vs baseline: 1.0946x; 1.0023x over previous
#include <cuda_runtime.h>
#include <cuda_bf16.h>
#include <cstdint>

#define Bb   128
#define Ss   416
#define Nn   32
#define Mm   384
#define Dd   256
#define Hh   8
#define Ee   32
#define Oo   256
#define BSs  (Bb*Ss)          // 53248
#define NBH  (Bb*Hh*Ss*Ee)    // 13,631,488

// -------- scratch (static device globals; no runtime allocation) ----------
// fragment-packed weights: [proj(5)][n8t(32)][kc(16)][lane(32)] x 16B
__device__ uint4 g_wf[5*32*16*32];
__device__ __nv_bfloat16 g_qh[NBH], g_ql[NBH];
__device__ __nv_bfloat16 g_kh[NBH], g_kl[NBH];
__device__ __nv_bfloat16 g_vh[NBH], g_vl[NBH];
__device__ float         g_g [NBH];
// fragment-packed attention output: [m8t(6656)][kc(16)][lane(32)] x 16B
__device__ uint4 g_aof[6656*16*32];

__device__ __forceinline__ float warpSum(float v) {
#pragma unroll
    for (int o = 16; o; o >>= 1) v += __shfl_xor_sync(0xffffffffu, v, o);
    return v;
}

// -------- mma.sync helpers --------------------------------------------------
__device__ __forceinline__ uint32_t smem_u32(const void* p) {
    uint32_t a;
    asm("{ .reg .u64 t; cvta.to.shared.u64 t, %1; cvt.u32.u64 %0, t; }"
        : "=r"(a) : "l"(p));
    return a;
}
__device__ __forceinline__ void ldsm4(uint32_t& r0, uint32_t& r1,
                                      uint32_t& r2, uint32_t& r3, uint32_t a) {
    asm volatile("ldmatrix.sync.aligned.m8n8.x4.shared.b16 {%0,%1,%2,%3}, [%4];"
                 : "=r"(r0), "=r"(r1), "=r"(r2), "=r"(r3) : "r"(a));
}
__device__ __forceinline__ void ldsm4t(uint32_t& r0, uint32_t& r1,
                                       uint32_t& r2, uint32_t& r3, uint32_t a) {
    asm volatile("ldmatrix.sync.aligned.m8n8.x4.trans.shared.b16 {%0,%1,%2,%3}, [%4];"
                 : "=r"(r0), "=r"(r1), "=r"(r2), "=r"(r3) : "r"(a));
}
__device__ __forceinline__ void ldsm2(uint32_t& r0, uint32_t& r1, uint32_t a) {
    asm volatile("ldmatrix.sync.aligned.m8n8.x2.shared.b16 {%0,%1}, [%2];"
                 : "=r"(r0), "=r"(r1) : "r"(a));
}
__device__ __forceinline__ void mma16816(float* d, const uint32_t* a,
                                         const uint32_t* b) {
    asm volatile(
        "mma.sync.aligned.m16n8k16.row.col.f32.bf16.bf16.f32 "
        "{%0,%1,%2,%3}, {%4,%5,%6,%7}, {%8,%9}, {%0,%1,%2,%3};"
        : "+f"(d[0]), "+f"(d[1]), "+f"(d[2]), "+f"(d[3])
        : "r"(a[0]), "r"(a[1]), "r"(a[2]), "r"(a[3]), "r"(b[0]), "r"(b[1]));
}
__device__ __forceinline__ void mma1688(float* d, const uint32_t* a, uint32_t b) {
    asm volatile(
        "mma.sync.aligned.m16n8k8.row.col.f32.bf16.bf16.f32 "
        "{%0,%1,%2,%3}, {%4,%5}, {%6}, {%0,%1,%2,%3};"
        : "+f"(d[0]), "+f"(d[1]), "+f"(d[2]), "+f"(d[3])
        : "r"(a[0]), "r"(a[1]), "r"(b));
}
__device__ __forceinline__ void packhl2(float x, float y,
                                        uint32_t& ph, uint32_t& pl) {
    asm("cvt.rn.bf16x2.f32 %0, %1, %2;" : "=r"(ph) : "f"(y), "f"(x));
    float xh = __uint_as_float(ph << 16);
    float yh = __uint_as_float(ph & 0xFFFF0000u);
    float xl = x - xh;
    float yl = y - yh;
    asm("cvt.rn.bf16x2.f32 %0, %1, %2;" : "=r"(pl) : "f"(yl), "f"(xl));
}
__device__ __forceinline__ float ex2f(float x) {
    float r; asm("ex2.approx.f32 %0, %1;" : "=f"(r) : "f"(x)); return r;
}
__device__ __forceinline__ void cpasync16(uint32_t dst, const void* src) {
    asm volatile("cp.async.cg.shared.global [%0], [%1], 16;"
                 :: "r"(dst), "l"(src) : "memory");
}
#define CP_COMMIT() asm volatile("cp.async.commit_group;" ::: "memory")
#define CP_WAIT1()  asm volatile("cp.async.wait_group 1;" ::: "memory")
#define CP_WAIT0()  asm volatile("cp.async.wait_group 0;" ::: "memory")

// ========== Kernel 0: weights -> fragment-packed hi/lo (g_wf) ==============
__global__ void k_wconv(const float* __restrict__ qp, const float* __restrict__ kp,
                        const float* __restrict__ vp, const float* __restrict__ gp,
                        const float* __restrict__ ow) {
    int n8t = blockIdx.x;      // 0..31
    int proj = blockIdx.y;     // 0..4
    int tid = threadIdx.x;     // 512
    int kc = tid >> 5, lane = tid & 31;
    int n = n8t * 8 + (lane >> 2);
    int k0 = kc * 16 + (lane & 3) * 2;
    float v0, v1, v8, v9;
    if (proj < 4) {
        const float* Wp = (proj == 0) ? qp : (proj == 1) ? kp
                         : (proj == 2) ? vp : gp;
        int base = (n >> 5) * 8192 + (n & 31);
        v0 = Wp[base + k0 * 32];
        v1 = Wp[base + (k0 + 1) * 32];
        v8 = Wp[base + (k0 + 8) * 32];
        v9 = Wp[base + (k0 + 9) * 32];
    } else {
        v0 = ow[k0 * 256 + n];
        v1 = ow[(k0 + 1) * 256 + n];
        v8 = ow[(k0 + 8) * 256 + n];
        v9 = ow[(k0 + 9) * 256 + n];
    }
    uint32_t ph0, pl0, ph1, pl1;
    packhl2(v0, v1, ph0, pl0);
    packhl2(v8, v9, ph1, pl1);
    g_wf[((proj * 32 + n8t) * 16 + kc) * 32 + lane] =
        make_uint4(ph0, ph1, pl0, pl1);
}

// ==== Kernel 2: QKVG; fused LN1 A-staging; B fragments reg-prefetched ======
#define QSCALE 0.2550868099f
#define QK_AHI 0
#define QK_ALO (128*264*2)                 // 67584
#define QKVG_SMEM (2*128*264*2)            // 135168

__global__ void __launch_bounds__(512, 1)
k_qkvg(const float* __restrict__ x, const float* __restrict__ gam,
       const float* __restrict__ bet) {
    extern __shared__ char smq[];
    __nv_bfloat16* Ahi = (__nv_bfloat16*)(smq + QK_AHI);
    __nv_bfloat16* Alo = (__nv_bfloat16*)(smq + QK_ALO);
    uint32_t ahi_b = smem_u32(Ahi), alo_b = smem_u32(Alo);

    int tid = threadIdx.x;
    int wid = tid >> 5, lane = tid & 31;
    int wm = wid >> 3, wn = wid & 7;       // 2 m-slices (64 rows) x 8 n-slices (16)
    int m0 = blockIdx.x * 128;

    // ---- stage A with fused LayerNorm: warp w handles rows w*8..w*8+7 ----
    {
        float4 gm0 = *(const float4*)&gam[lane * 8];
        float4 gm1 = *(const float4*)&gam[lane * 8 + 4];
        float4 bt0 = *(const float4*)&bet[lane * 8];
        float4 bt1 = *(const float4*)&bet[lane * 8 + 4];
#pragma unroll
        for (int r = 0; r < 8; r++) {
            int row = wid * 8 + r;
            const float* xr = x + (size_t)(m0 + row) * 256 + lane * 8;
            float4 v0 = *(const float4*)xr;
            float4 v1 = *(const float4*)(xr + 4);
            float s = v0.x + v0.y + v0.z + v0.w + v1.x + v1.y + v1.z + v1.w;
            s = warpSum(s);
            float mu = s * (1.f / 256.f);
            float d[8] = {v0.x - mu, v0.y - mu, v0.z - mu, v0.w - mu,
                          v1.x - mu, v1.y - mu, v1.z - mu, v1.w - mu};
            float vs = 0.f;
#pragma unroll
            for (int i = 0; i < 8; i++) vs += d[i] * d[i];
            vs = warpSum(vs);
            float rs = rsqrtf(vs * (1.f / 256.f) + 1e-6f);
            float o[8];
            o[0] = d[0] * rs * gm0.x + bt0.x;
            o[1] = d[1] * rs * gm0.y + bt0.y;
            o[2] = d[2] * rs * gm0.z + bt0.z;
            o[3] = d[3] * rs * gm0.w + bt0.w;
            o[4] = d[4] * rs * gm1.x + bt1.x;
            o[5] = d[5] * rs * gm1.y + bt1.y;
            o[6] = d[6] * rs * gm1.z + bt1.z;
            o[7] = d[7] * rs * gm1.w + bt1.w;
            uint32_t ph[4], pl[4];
#pragma unroll
            for (int i = 0; i < 4; i++) packhl2(o[i*2], o[i*2+1], ph[i], pl[i]);
            *(uint4*)&Ahi[row * 264 + lane * 8] = *(uint4*)ph;
            *(uint4*)&Alo[row * 264 + lane * 8] = *(uint4*)pl;
        }
    }
    __syncthreads();   // the ONLY block barrier

    int a_row = lane & 15;
    int a_kof = (lane >> 4) * 8;
    int fr = lane >> 2, fc = lane & 3;

    // hoisted epilogue bases (nt-invariant)
    size_t base1[4], base2[4];
#pragma unroll
    for (int mt = 0; mt < 4; mt++) {
        int m = m0 + wm * 64 + mt * 16 + fr;
        int b1 = m / Ss, s1 = m - b1 * Ss;
        int m2 = m + 8;
        int b2 = m2 / Ss, s2 = m2 - b2 * Ss;
        base1[mt] = ((size_t)b1 * Hh * Ss + s1) * Ee;
        base2[mt] = ((size_t)b2 * Hh * Ss + s2) * Ee;
    }

    // prefetch B for nt = 0
    uint4 bf[2];
    {
        const uint4* pb0 = g_wf + ((size_t)(0 * 32 + 0 * 16 + wn * 2) * 16) * 32 + lane;
        bf[0] = pb0[0];
        bf[1] = pb0[512];
    }

    for (int nt = 0; nt < 8; nt++) {
        int proj = nt >> 1;
        int nin = (nt & 1) * 128;
        int n8b = proj * 32 + (nt & 1) * 16 + wn * 2;
        const uint4* pb = g_wf + ((size_t)n8b * 16) * 32 + lane;
        int ntn = nt + 1;
        const uint4* pbn = g_wf + ((size_t)((ntn >> 1) * 32 + (ntn & 1) * 16
                                           + wn * 2) * 16) * 32 + lane;

        float acc[4][2][4];
#pragma unroll
        for (int mt = 0; mt < 4; mt++)
#pragma unroll
            for (int j = 0; j < 2; j++)
#pragma unroll
                for (int c = 0; c < 4; c++) acc[mt][j][c] = 0.f;

#pragma unroll 2
        for (int kc = 0; kc < 16; kc++) {
            uint4 bfn[2];
            if (kc < 15) {
                bfn[0] = pb[(kc + 1) * 32];
                bfn[1] = pb[512 + (kc + 1) * 32];
            } else if (nt < 7) {
                bfn[0] = pbn[0];
                bfn[1] = pbn[512];
            }
            uint32_t ah[4][4], al[4][4];
#pragma unroll
            for (int mt = 0; mt < 4; mt++) {
                uint32_t off = (uint32_t)((wm * 64 + mt * 16 + a_row) * 264
                                          + kc * 16 + a_kof) * 2;
                ldsm4(ah[mt][0], ah[mt][1], ah[mt][2], ah[mt][3], ahi_b + off);
                ldsm4(al[mt][0], al[mt][1], al[mt][2], al[mt][3], alo_b + off);
            }
#pragma unroll
            for (int mt = 0; mt < 4; mt++)
#pragma unroll
                for (int j = 0; j < 2; j++) {
                    uint32_t bh[2] = {bf[j].x, bf[j].y};
                    uint32_t bl[2] = {bf[j].z, bf[j].w};
                    mma16816(acc[mt][j], ah[mt], bh);
                    mma16816(acc[mt][j], ah[mt], bl);
                    mma16816(acc[mt][j], al[mt], bh);
                }
            bf[0] = bfn[0];
            bf[1] = bfn[1];
        }

        if (proj == 0) {
#pragma unroll
            for (int mt = 0; mt < 4; mt++)
#pragma unroll
                for (int j = 0; j < 2; j++)
#pragma unroll
                    for (int c = 0; c < 4; c++) acc[mt][j][c] *= QSCALE;
        }

        __nv_bfloat16* Oh = (proj == 0) ? g_qh : (proj == 1) ? g_kh : g_vh;
        __nv_bfloat16* Ol = (proj == 0) ? g_ql : (proj == 1) ? g_kl : g_vl;
        bool isG = (proj == 3);
#pragma unroll
        for (int mt = 0; mt < 4; mt++) {
#pragma unroll
            for (int j = 0; j < 2; j++) {
                int n = nin + wn * 16 + j * 8 + fc * 2;
                int h = n >> 5, e = n & 31;
                size_t hoff = (size_t)h * (Ss * Ee) + e;
                size_t i1 = base1[mt] + hoff;
                size_t i2 = base2[mt] + hoff;
                if (isG) {
                    *(float2*)&g_g[i1] = make_float2(acc[mt][j][0], acc[mt][j][1]);
                    *(float2*)&g_g[i2] = make_float2(acc[mt][j][2], acc[mt][j][3]);
                } else {
                    uint32_t h1, l1, h2, l2;
                    packhl2(acc[mt][j][0], acc[mt][j][1], h1, l1);
                    packhl2(acc[mt][j][2], acc[mt][j][3], h2, l2);
                    *(uint32_t*)&Oh[i1] = h1;
                    *(uint32_t*)&Ol[i1] = l1;
                    *(uint32_t*)&Oh[i2] = h2;
                    *(uint32_t*)&Ol[i2] = l2;
                }
            }
        }
    }
}

// ==== Kernel 3: attention; 2 groups, Q via LDG, log2-domain softmax ========
#define KHI_OFF   0
#define KLO_OFF   33280
#define VH_OFF    66560
#define VL_OFF    99840
#define CSH_OFF   133120
#define RED_OFF   134784
#define OP_OFF    136832
#define ATTN_SMEM 169600

__global__ void __launch_bounds__(512, 1)
k_attn(const float* __restrict__ pmask, const float* __restrict__ mmask) {
    extern __shared__ char smc[];
    __nv_bfloat16* khi = (__nv_bfloat16*)(smc + KHI_OFF);
    __nv_bfloat16* klo = (__nv_bfloat16*)(smc + KLO_OFF);
    __nv_bfloat16* v_h = (__nv_bfloat16*)(smc + VH_OFF);
    __nv_bfloat16* v_l = (__nv_bfloat16*)(smc + VL_OFF);
    float*         c_sh = (float*)(smc + CSH_OFF);
    float*         red  = (float*)(smc + RED_OFF);
    float*         opart = (float*)(smc + OP_OFF);

    uint32_t khi_b = smem_u32(khi), klo_b = smem_u32(klo);
    uint32_t vh_b = smem_u32(v_h), vl_b = smem_u32(v_l);

    int tid = threadIdx.x;
    int lane = tid & 31;
    int bh = blockIdx.x;
    int h = bh & 7, b = bh >> 3;
    size_t baseBH = (size_t)(b * Hh + h) * Ss;

    for (int i = tid; i < Ss * 4; i += 512) {
        int y = i >> 2, q = i & 3;
        size_t src = (baseBH + y) * Ee + q * 8;
        *(uint4*)&khi[y * 40 + q * 8] = *(const uint4*)&g_kh[src];
        *(uint4*)&klo[y * 40 + q * 8] = *(const uint4*)&g_kl[src];
        *(uint4*)&v_h[y * 40 + q * 8] = *(const uint4*)&g_vh[src];
        *(uint4*)&v_l[y * 40 + q * 8] = *(const uint4*)&g_vl[src];
    }
    for (int i = tid; i < Ss; i += 512) {
        float val = (i < Nn) ? pmask[b * Nn + i] : mmask[b * Mm + (i - Nn)];
        c_sh[i] = (val == -2.0f) ? 0.f : 1.f;
    }
    __syncthreads();

    const float BIGL = 1.0e9f;
    int grp = tid >> 8;
    int wg = (tid >> 5) & 7;
    int mh = (wg >> 2) & 1;
    int nq = wg & 3;
    int nbase = nq * 104;
    int gtid = tid & 255;

    int b_row = ((lane >> 4) & 1) * 8 + (lane & 7);
    int b_kof = ((lane >> 3) & 1) * 8;
    int fr = lane >> 2, fc = lane & 3;
    int lx1 = mh * 16 + fr;
    int lx2 = lx1 + 8;

    float* redg = red + grp * 256;
    float* opg  = opart + grp * 4096;
    int bar_id = grp + 1;

    for (int t = grp; t < 13; t += 2) {
        int x0 = t * 32;

        uint32_t qah[2][4], qal[2][4];
        {
            const __nv_bfloat16* ph = g_qh + (baseBH + x0 + lx1) * 32;
            const __nv_bfloat16* pl = g_ql + (baseBH + x0 + lx1) * 32;
#pragma unroll
            for (int ks = 0; ks < 2; ks++) {
                int kk = ks * 16 + fc * 2;
                qah[ks][0] = *(const uint32_t*)&ph[kk];
                qah[ks][1] = *(const uint32_t*)&ph[256 + kk];
                qah[ks][2] = *(const uint32_t*)&ph[kk + 8];
                qah[ks][3] = *(const uint32_t*)&ph[256 + kk + 8];
                qal[ks][0] = *(const uint32_t*)&pl[kk];
                qal[ks][1] = *(const uint32_t*)&pl[256 + kk];
                qal[ks][2] = *(const uint32_t*)&pl[kk + 8];
                qal[ks][3] = *(const uint32_t*)&pl[256 + kk + 8];
            }
        }

        float acc[13][4];
#pragma unroll
        for (int t2 = 0; t2 < 13; t2++)
#pragma unroll
            for (int c = 0; c < 4; c++) acc[t2][c] = 0.f;

#pragma unroll
        for (int ks = 0; ks < 2; ks++) {
            int kk = ks * 16;
#pragma unroll
            for (int jp = 0; jp < 6; jp++) {
                uint32_t bh2[4], bl2[4];
                uint32_t off = (uint32_t)((nbase + jp * 16 + b_row) * 40
                                          + kk + b_kof) * 2;
                ldsm4(bh2[0], bh2[1], bh2[2], bh2[3], khi_b + off);
                ldsm4(bl2[0], bl2[1], bl2[2], bl2[3], klo_b + off);
                mma16816(acc[jp*2],   qah[ks], &bh2[0]);
                mma16816(acc[jp*2],   qah[ks], &bl2[0]);
                mma16816(acc[jp*2],   qal[ks], &bh2[0]);
                mma16816(acc[jp*2+1], qah[ks], &bh2[2]);
                mma16816(acc[jp*2+1], qah[ks], &bl2[2]);
                mma16816(acc[jp*2+1], qal[ks], &bh2[2]);
            }
            {
                uint32_t bh1[2], bl1[2];
                uint32_t off = (uint32_t)((nbase + 96 + (lane & 7)) * 40 + kk
                                          + 8 * ((lane >> 3) & 1)) * 2;
                ldsm2(bh1[0], bh1[1], khi_b + off);
                ldsm2(bl1[0], bl1[1], klo_b + off);
                mma16816(acc[12], qah[ks], bh1);
                mma16816(acc[12], qah[ks], bl1);
                mma16816(acc[12], qal[ks], bh1);
            }
        }

        bool xIsP = (t == 0);
        float cx1 = c_sh[x0 + lx1];
        float cx2 = c_sh[x0 + lx2];
#pragma unroll
        for (int t2 = 0; t2 < 13; t2++) {
            int ybase = nbase + t2 * 8;
            int yc = ybase + fc * 2;
            bool cross = (xIsP != (ybase < Nn));
            float cy0 = c_sh[yc], cy1 = c_sh[yc + 1];
            float by0 = cross ? fmaf(cy0, BIGL, -BIGL) : -BIGL;
            float by1 = cross ? fmaf(cy1, BIGL, -BIGL) : -BIGL;
            acc[t2][0] += by0;
            acc[t2][1] += by1;
            acc[t2][2] += by0;
            acc[t2][3] += by1;
        }

        float m1 = -3.0e38f, m2 = -3.0e38f;
#pragma unroll
        for (int t2 = 0; t2 < 13; t2++) {
            m1 = fmaxf(m1, fmaxf(acc[t2][0], acc[t2][1]));
            m2 = fmaxf(m2, fmaxf(acc[t2][2], acc[t2][3]));
        }
#pragma unroll
        for (int o = 1; o <= 2; o <<= 1) {
            m1 = fmaxf(m1, __shfl_xor_sync(0xffffffffu, m1, o));
            m2 = fmaxf(m2, __shfl_xor_sync(0xffffffffu, m2, o));
        }
        float s1 = 0.f, s2 = 0.f;
#pragma unroll
        for (int t2 = 0; t2 < 13; t2++) {
            acc[t2][0] = ex2f(acc[t2][0] - m1);
            acc[t2][1] = ex2f(acc[t2][1] - m1);
            acc[t2][2] = ex2f(acc[t2][2] - m2);
            acc[t2][3] = ex2f(acc[t2][3] - m2);
            s1 += acc[t2][0] + acc[t2][1];
            s2 += acc[t2][2] + acc[t2][3];
        }
#pragma unroll
        for (int o = 1; o <= 2; o <<= 1) {
            s1 += __shfl_xor_sync(0xffffffffu, s1, o);
            s2 += __shfl_xor_sync(0xffffffffu, s2, o);
        }
        if (fc == 0) {
            redg[lx1 * 8 + nq * 2]     = m1;
            redg[lx1 * 8 + nq * 2 + 1] = s1;
            redg[lx2 * 8 + nq * 2]     = m2;
            redg[lx2 * 8 + nq * 2 + 1] = s2;
        }
        asm volatile("bar.sync %0, %1;" :: "r"(bar_id), "r"(256) : "memory");
        float f1, f2;
        {
            float M1 = -3.0e38f, M2 = -3.0e38f;
#pragma unroll
            for (int q = 0; q < 4; q++) {
                M1 = fmaxf(M1, redg[lx1 * 8 + q * 2]);
                M2 = fmaxf(M2, redg[lx2 * 8 + q * 2]);
            }
            float S1 = 0.f, S2 = 0.f;
#pragma unroll
            for (int q = 0; q < 4; q++) {
                S1 += redg[lx1 * 8 + q * 2 + 1] * ex2f(redg[lx1 * 8 + q * 2] - M1);
                S2 += redg[lx2 * 8 + q * 2 + 1] * ex2f(redg[lx2 * 8 + q * 2] - M2);
            }
            f1 = cx1 * ex2f(m1 - M1) / S1;
            f2 = cx2 * ex2f(m2 - M2) / S2;
        }

        {
            float o[4][4];
#pragma unroll
            for (int eg = 0; eg < 4; eg++)
#pragma unroll
                for (int c = 0; c < 4; c++) o[eg][c] = 0.f;

#pragma unroll
            for (int g = 0; g < 3; g++) {
                uint32_t Ah0[4], Al0[4], Ah1[4], Al1[4];
                {
                    int ta = 4 * g, tb = 4 * g + 1;
                    packhl2(acc[ta][0] * f1, acc[ta][1] * f1, Ah0[0], Al0[0]);
                    packhl2(acc[ta][2] * f2, acc[ta][3] * f2, Ah0[1], Al0[1]);
                    packhl2(acc[tb][0] * f1, acc[tb][1] * f1, Ah0[2], Al0[2]);
                    packhl2(acc[tb][2] * f2, acc[tb][3] * f2, Ah0[3], Al0[3]);
                    int tc = 4 * g + 2, td = 4 * g + 3;
                    packhl2(acc[tc][0] * f1, acc[tc][1] * f1, Ah1[0], Al1[0]);
                    packhl2(acc[tc][2] * f2, acc[tc][3] * f2, Ah1[1], Al1[1]);
                    packhl2(acc[td][0] * f1, acc[td][1] * f1, Ah1[2], Al1[2]);
                    packhl2(acc[td][2] * f2, acc[td][3] * f2, Ah1[3], Al1[3]);
                }
#pragma unroll
                for (int eg = 0; eg < 4; eg++) {
                    uint32_t bh4[4], bl4[4];
                    uint32_t offB = (uint32_t)((nbase + g * 32 + lane) * 40
                                               + eg * 8) * 2;
                    ldsm4t(bh4[0], bh4[1], bh4[2], bh4[3], vh_b + offB);
                    ldsm4t(bl4[0], bl4[1], bl4[2], bl4[3], vl_b + offB);
                    mma16816(o[eg], Ah0, &bh4[0]);
                    mma16816(o[eg], Ah0, &bl4[0]);
                    mma16816(o[eg], Al0, &bh4[0]);
                    mma16816(o[eg], Ah1, &bh4[2]);
                    mma16816(o[eg], Ah1, &bl4[2]);
                    mma16816(o[eg], Al1, &bh4[2]);
                }
            }
            {
                uint32_t Ath[2], Atl[2];
                packhl2(acc[12][0] * f1, acc[12][1] * f1, Ath[0], Atl[0]);
                packhl2(acc[12][2] * f2, acc[12][3] * f2, Ath[1], Atl[1]);
                uint32_t bh4[4], bl4[4];
                uint32_t offT = (uint32_t)((nbase + 96 + (lane & 7)) * 40
                                           + (lane >> 3) * 8) * 2;
                ldsm4t(bh4[0], bh4[1], bh4[2], bh4[3], vh_b + offT);
                ldsm4t(bl4[0], bl4[1], bl4[2], bl4[3], vl_b + offT);
#pragma unroll
                for (int eg = 0; eg < 4; eg++) {
                    mma1688(o[eg], Ath, bh4[eg]);
                    mma1688(o[eg], Ath, bl4[eg]);
                    mma1688(o[eg], Atl, bh4[eg]);
                }
            }
            float* op = opg + nq * 1024;
#pragma unroll
            for (int eg = 0; eg < 4; eg++) {
                int e = eg * 8 + fc * 2;
                *(float2*)&op[lx1 * 32 + e] = make_float2(o[eg][0], o[eg][1]);
                *(float2*)&op[lx2 * 32 + e] = make_float2(o[eg][2], o[eg][3]);
            }
        }
        asm volatile("bar.sync %0, %1;" :: "r"(bar_id), "r"(256) : "memory");

        // ---- reduce over nq + gate + store (fragment-packed g_aof) ----
#pragma unroll
        for (int it = 0; it < 2; it++) {
            int idx = gtid + it * 256;
            int row = idx >> 4;
            int e = (idx & 15) * 2;
            const float* op = opg + row * 32 + e;
            float sum0 = op[0] + op[1024] + op[2048] + op[3072];
            float sum1 = op[1] + op[1025] + op[2049] + op[3073];
            int xs_ = x0 + row;
            float2 gv = *(const float2*)&g_g[(baseBH + xs_) * Ee + e];
            float sg0 = 1.f / (1.f + __expf(-gv.x));
            float sg1 = 1.f / (1.f + __expf(-gv.y));
            float o0 = sum0 * sg0;
            float o1 = sum1 * sg1;
            uint32_t oh, ol;
            packhl2(o0, o1, oh, ol);
            int grow = b * Ss + xs_;
            int m8t = grow >> 3;
            int kglob = h * 32 + e;
            int kc = kglob >> 4;
            int p = (kglob & 15) >> 1;
            int lane2 = (grow & 7) * 4 + (p & 3);
            int slot = p >> 2;
            uint32_t* dst = (uint32_t*)g_aof
                          + ((size_t)(m8t * 16 + kc) * 32 + lane2) * 4;
            dst[slot]     = oh;
            dst[slot + 2] = ol;
        }
    }
}

// ==== Kernel 4: output proj + LN2; 2 kc per stage, reg-prefetched A ========
#define OBS_OFF 0                             // 2 stages x 32768 B
#define OYS_OFF 65536                         // 64*264*4 = 67584
#define OMU_OFF 133120
#define ORS_OFF 133376
#define OLN_SMEM 133632

__global__ void __launch_bounds__(512, 1)
k_outln(const float* __restrict__ bias, const float* __restrict__ g2,
        const float* __restrict__ b2, float* __restrict__ out) {
    extern __shared__ char smo[];
    uint4* Bs = (uint4*)(smo + OBS_OFF);      // [stage][kc2(2)][n8t(32)][lane(32)]
    float* ys  = (float*)(smo + OYS_OFF);
    float* mus = (float*)(smo + OMU_OFF);
    float* rss = (float*)(smo + ORS_OFF);
    uint32_t bs_b = smem_u32(Bs);

    int tid = threadIdx.x;
    int wid = tid >> 5, lane = tid & 31;
    int mh = wid & 3, nq = wid >> 2;          // 4 m-slices(16) x 4 n-quarters(64)
    int r0 = blockIdx.x * 64;
    int fr = lane >> 2, fc = lane & 3;
    int t0 = (r0 >> 3) + mh * 2;

    const uint4* pa0 = g_aof + (size_t)t0 * 16 * 32 + lane;
    const uint4* pa1 = pa0 + 16 * 32;

    // stage = 2 k-chunks (kc = 2*st, 2*st+1)
    auto prefetchB = [&](int st, int buf) {
#pragma unroll
        for (int it = 0; it < 4; it++) {
            int idx = tid + it * 512;          // 0..2047
            int kc = 2 * st + (idx >> 10);
            int sub = idx & 1023;              // n8t*32 + lane
            cpasync16(bs_b + (uint32_t)(buf * 2048 + idx) * 16,
                      &g_wf[((size_t)(4 * 32 + (sub >> 5)) * 16 + kc) * 32
                            + (sub & 31)]);
        }
        CP_COMMIT();
    };
    prefetchB(0, 0);

    float acc[8][4];
#pragma unroll
    for (int j = 0; j < 8; j++)
#pragma unroll
        for (int c = 0; c < 4; c++) acc[j][c] = 0.f;

    // register-prefetched A fragments for both kc of the current stage
    uint4 ea0 = pa0[0],  eb0 = pa1[0];
    uint4 ea1 = pa0[32], eb1 = pa1[32];

    for (int st = 0; st < 8; st++) {
        if (st < 7) { prefetchB(st + 1, (st + 1) & 1); CP_WAIT1(); }
        else        { CP_WAIT0(); }
        __syncthreads();

        uint4 na0, nb0, na1, nb1;
        if (st < 7) {
            na0 = pa0[(2 * st + 2) * 32];
            nb0 = pa1[(2 * st + 2) * 32];
            na1 = pa0[(2 * st + 3) * 32];
            nb1 = pa1[(2 * st + 3) * 32];
        }

        const uint4* bst = Bs + (st & 1) * 2048;
        {
            uint32_t Ahf[4] = {ea0.x, eb0.x, ea0.y, eb0.y};
            uint32_t Alf[4] = {ea0.z, eb0.z, ea0.w, eb0.w};
#pragma unroll
            for (int jp = 0; jp < 8; jp++) {
                uint4 bfq = bst[(nq * 8 + jp) * 32 + lane];
                uint32_t bh[2] = {bfq.x, bfq.y};
                uint32_t bl[2] = {bfq.z, bfq.w};
                mma16816(acc[jp], Ahf, bh);
                mma16816(acc[jp], Ahf, bl);
                mma16816(acc[jp], Alf, bh);
            }
        }
        {
            uint32_t Ahf[4] = {ea1.x, eb1.x, ea1.y, eb1.y};
            uint32_t Alf[4] = {ea1.z, eb1.z, ea1.w, eb1.w};
#pragma unroll
            for (int jp = 0; jp < 8; jp++) {
                uint4 bfq = bst[1024 + (nq * 8 + jp) * 32 + lane];
                uint32_t bh[2] = {bfq.x, bfq.y};
                uint32_t bl[2] = {bfq.z, bfq.w};
                mma16816(acc[jp], Ahf, bh);
                mma16816(acc[jp], Ahf, bl);
                mma16816(acc[jp], Alf, bh);
            }
        }
        __syncthreads();
        ea0 = na0; eb0 = nb0; ea1 = na1; eb1 = nb1;
    }

    int lx1 = mh * 16 + fr;
    int lx2 = lx1 + 8;
#pragma unroll
    for (int j = 0; j < 8; j++) {
        int n = nq * 64 + j * 8 + fc * 2;
        float b0 = bias[n], b1 = bias[n + 1];
        ys[lx1 * 264 + n]     = acc[j][0] + b0;
        ys[lx1 * 264 + n + 1] = acc[j][1] + b1;
        ys[lx2 * 264 + n]     = acc[j][2] + b0;
        ys[lx2 * 264 + n + 1] = acc[j][3] + b1;
    }
    __syncthreads();

#pragma unroll
    for (int rr = 0; rr < 4; rr++) {
        int xr = wid + rr * 16;
        const float* row = ys + xr * 264;
        float s = 0.f;
#pragma unroll
        for (int j = 0; j < 8; j++) s += row[lane + 32 * j];
        s = warpSum(s);
        float mu = s * (1.f / 256.f);
        float vs = 0.f;
#pragma unroll
        for (int j = 0; j < 8; j++) {
            float d = row[lane + 32 * j] - mu;
            vs += d * d;
        }
        vs = warpSum(vs);
        if (lane == 0) { mus[xr] = mu; rss[xr] = rsqrtf(vs * (1.f / 256.f) + 1e-6f); }
    }
    __syncthreads();

    int cc = tid & 255;
    int rh = tid >> 8;
    float gt = g2[cc], bt = b2[cc];
#pragma unroll 4
    for (int r = rh * 32; r < rh * 32 + 32; r++) {
        out[(size_t)(r0 + r) * 256 + cc] =
            (ys[r * 264 + cc] - mus[r]) * rss[r] * gt + bt;
    }
}

// ===========================================================================
extern "C" void kernel_launch(void* const* d_in, const int* in_sizes, int n_in,
                              void* d_out, int out_size) {
    const float* x   = (const float*)d_in[0];
    const float* pm  = (const float*)d_in[1];
    const float* mm  = (const float*)d_in[2];
    const float* qp  = (const float*)d_in[3];
    const float* kp  = (const float*)d_in[4];
    const float* vp  = (const float*)d_in[5];
    const float* gp  = (const float*)d_in[6];
    const float* ow  = (const float*)d_in[7];
    const float* ob  = (const float*)d_in[8];
    const float* l1g = (const float*)d_in[9];
    const float* l1b = (const float*)d_in[10];
    const float* l2g = (const float*)d_in[11];
    const float* l2b = (const float*)d_in[12];
    float* out = (float*)d_out;

    cudaFuncSetAttribute(k_qkvg, cudaFuncAttributeMaxDynamicSharedMemorySize,
                         QKVG_SMEM);
    cudaFuncSetAttribute(k_attn, cudaFuncAttributeMaxDynamicSharedMemorySize,
                         ATTN_SMEM);
    cudaFuncSetAttribute(k_outln, cudaFuncAttributeMaxDynamicSharedMemorySize,
                         OLN_SMEM);

    k_wconv<<<dim3(32, 5), 512>>>(qp, kp, vp, gp, ow);
    k_qkvg <<<416, 512, QKVG_SMEM>>>(x, l1g, l1b);
    k_attn <<<Bb * Hh, 512, ATTN_SMEM>>>(pm, mm);
    k_outln<<<BSs / 64, 512, OLN_SMEM>>>(ob, l2g, l2b, out);
}